// round 14
// baseline (speedup 1.0000x reference)
#include <cuda_runtime.h>
#include <cuda_fp16.h>
#include <math.h>
#include <stdint.h>

// ---------------------------------------------------------------------------
// SpectralDiscriminator on GB300 — fp16 mma.sync GEMMs + flash-fused attention.
// R14: flash inner barriers scoped to warp row-groups (named bar.sync) —
//      only the stage-buffer barrier remains CTA-wide.
// ---------------------------------------------------------------------------

#define NPIX 4096
#define BATCH 4
#define ESHIFT 4.0f

__device__ __half g_a1 [BATCH * NPIX * 64];
__device__ __half g_a3 [BATCH * NPIX * 256];
__device__ __half g_qk [BATCH * NPIX * 128];          // [pix][128]: q|k (+pad for attn1)
__device__ __half g_v  [BATCH * 512 * NPIX];          // channel-major [c][pix]
__device__ __half g_t1 [BATCH * NPIX * 256];
__device__ __half g_t2 [BATCH * NPIX * 512];
__device__ __half g_a4 [BATCH * NPIX * 512];
__device__ float g_sig[8];
__device__ float g_qkb1[128];
__device__ float g_qkb2[128];
__device__ __half g_W2h[128 * 64];
__device__ __half g_W3h[256 * 128];
__device__ __half g_W4h[512 * 256];
__device__ __half g_qkv1h[384 * 256];   // [q32|k32|pad64|v256] x 256
__device__ __half g_qkv2h[640 * 512];   // [q64|k64|v512] x 512

__device__ __forceinline__ uint32_t smem_u32(const void* p) {
    uint32_t a;
    asm("{ .reg .u64 t; cvta.to.shared.u64 t, %1; cvt.u32.u64 %0, t; }" : "=r"(a) : "l"(p));
    return a;
}

#define LDMX4(r0, r1, r2, r3, ad) \
    asm volatile("ldmatrix.sync.aligned.m8n8.x4.shared.b16 {%0,%1,%2,%3}, [%4];\n" \
        : "=r"(r0), "=r"(r1), "=r"(r2), "=r"(r3) : "r"(ad))

#define MMA16816(d, a, b0, b1) \
    asm volatile("mma.sync.aligned.m16n8k16.row.col.f32.f16.f16.f32 " \
        "{%0,%1,%2,%3}, {%4,%5,%6,%7}, {%8,%9}, {%0,%1,%2,%3};\n" \
        : "+f"((d)[0]), "+f"((d)[1]), "+f"((d)[2]), "+f"((d)[3]) \
        : "r"((a)[0]), "r"((a)[1]), "r"((a)[2]), "r"((a)[3]), "r"(b0), "r"(b1))

#define CPA16(dst, src) \
    asm volatile("cp.async.cg.shared.global [%0], [%1], 16;\n" :: "r"(dst), "l"(src))

#define GBAR(id) asm volatile("bar.sync %0, 128;\n" :: "r"(id) : "memory")

// cp.async one 128-row x 64-half tile into SW128 smem (128B rows)
__device__ __forceinline__ void cpa_tile(uint32_t dstBase, const __half* src, int ld,
                                         int Rall, int r0, int K, int k0, int tid) {
    #pragma unroll
    for (int i = 0; i < 4; i++) {
        int e = tid + i * 256;
        int r = e >> 3, c = e & 7;
        int gr = r0 + r;
        uint32_t dst = dstBase + r * 128 + ((c ^ (r & 7)) << 4);
        bool ok = (gr < Rall) && (k0 + c * 8 < K);
        const __half* g = src + (ok ? ((size_t)gr * ld + k0 + c * 8) : 0);
        int bytes = ok ? 16 : 0;
        asm volatile("cp.async.cg.shared.global [%0], [%1], 16, %2;\n"
                     :: "r"(dst), "l"(g), "r"(bytes));
    }
}

// ---------------------------------------------------------------------------
// fp16 GEMM: C[m][n] = sum_k A[m,k]*B[n,k]. x = n-tile (fast), y = m-tile.
// EPI: 0 leaky(acc+bias[n]) -> fp16
//      7 merged qkv: blockIdx.x < qkTiles -> acc+bias[n] plain to Ch (ldc);
//                    else -> acc+vbias transposed to C2[(n-128)*NPIX+m] via bounce
// ---------------------------------------------------------------------------
template<int EPI>
__global__ void __launch_bounds__(256, 2)
hgemm(const __half* __restrict__ A, const __half* __restrict__ B,
      __half* __restrict__ Ch, __half* __restrict__ C2,
      int Mall, int Nall, int K, int lda, int ldb, int ldc,
      size_t sA, size_t sB, size_t sC, size_t sC2, int qkTiles,
      const float* __restrict__ bias, const float* __restrict__ vbias)
{
    extern __shared__ char smem[];
    uint32_t sbase = smem_u32(smem);
    const uint32_t stageSz = 32768;

    int tid = threadIdx.x, lane = tid & 31, wid = tid >> 5;
    int bz = blockIdx.z;
    A += sA * bz;  B += sB * bz;

    int m0 = blockIdx.y * 128;
    int n0 = blockIdx.x * 128;
    int wm = (wid & 3) * 32;
    int wn = (wid >> 2) * 64;

    float acc[2][8][4];
    #pragma unroll
    for (int a = 0; a < 2; a++)
        #pragma unroll
        for (int b = 0; b < 8; b++)
            #pragma unroll
            for (int c = 0; c < 4; c++) acc[a][b][c] = 0.f;

    int nkt = (K + 63) >> 6;

    #pragma unroll
    for (int s = 0; s < 2; s++) {
        if (s < nkt) {
            uint32_t b = sbase + s * stageSz;
            cpa_tile(b, A, lda, Mall, m0, K, s * 64, tid);
            cpa_tile(b + 16384, B, ldb, Nall, n0, K, s * 64, tid);
        }
        asm volatile("cp.async.commit_group;\n");
    }

    for (int kt = 0; kt < nkt; kt++) {
        asm volatile("cp.async.wait_group 1;\n");
        __syncthreads();

        uint32_t Ab = sbase + (kt % 3) * stageSz;
        uint32_t Bb = Ab + 16384;

        int kl = K - kt * 64;
        int nks = (kl >= 64) ? 4 : ((kl + 15) >> 4);

        #pragma unroll 4
        for (int ks = 0; ks < nks; ks++) {
            int c0 = ks * 2;
            uint32_t af[2][4];
            #pragma unroll
            for (int mt = 0; mt < 2; mt++) {
                int lr = wm + mt * 16 + (lane & 15);
                int lc = c0 + (lane >> 4);
                LDMX4(af[mt][0], af[mt][1], af[mt][2], af[mt][3],
                      Ab + lr * 128 + ((lc ^ (lr & 7)) << 4));
            }
            uint32_t bf[8][2];
            #pragma unroll
            for (int j = 0; j < 4; j++) {
                int nb_ = wn + j * 16;
                int lr = nb_ + (lane & 7) + ((lane >> 4) << 3);
                int lc = c0 + ((lane >> 3) & 1);
                LDMX4(bf[2*j][0], bf[2*j][1], bf[2*j+1][0], bf[2*j+1][1],
                      Bb + lr * 128 + ((lc ^ (lr & 7)) << 4));
            }
            #pragma unroll
            for (int mt = 0; mt < 2; mt++)
                #pragma unroll
                for (int nt = 0; nt < 8; nt++)
                    MMA16816(acc[mt][nt], af[mt], bf[nt][0], bf[nt][1]);
        }

        int nx = kt + 2;
        if (nx < nkt) {
            uint32_t b = sbase + (nx % 3) * stageSz;
            cpa_tile(b, A, lda, Mall, m0, K, nx * 64, tid);
            cpa_tile(b + 16384, B, ldb, Nall, n0, K, nx * 64, tid);
        }
        asm volatile("cp.async.commit_group;\n");
    }

    int g = lane >> 2, tg = lane & 3;

    if (EPI == 7) {
        if ((int)blockIdx.x < qkTiles) {
            __half* Cp = Ch + sC * bz;
            #pragma unroll
            for (int mt = 0; mt < 2; mt++)
            #pragma unroll
            for (int h = 0; h < 2; h++) {
                int row = m0 + wm + mt * 16 + g + h * 8;
                #pragma unroll
                for (int nt = 0; nt < 8; nt++) {
                    int col = n0 + wn + nt * 8 + tg * 2;
                    float v0 = acc[mt][nt][h * 2 + 0] + bias[col];
                    float v1 = acc[mt][nt][h * 2 + 1] + bias[col + 1];
                    *(__half2*)&Cp[(size_t)row * ldc + col] = __floats2half2_rn(v0, v1);
                }
            }
        } else {
            int vbase = n0 - qkTiles * 128;
            asm volatile("cp.async.wait_group 0;\n");
            __syncthreads();
            float* st = (float*)smem;
            #pragma unroll
            for (int mt = 0; mt < 2; mt++)
            #pragma unroll
            for (int h = 0; h < 2; h++) {
                int rl = wm + mt * 16 + g + h * 8;
                #pragma unroll
                for (int nt = 0; nt < 8; nt++) {
                    int cl = wn + nt * 8 + tg * 2;
                    st[cl * 132 + rl]       = acc[mt][nt][h * 2 + 0] + vbias[vbase + cl];
                    st[(cl + 1) * 132 + rl] = acc[mt][nt][h * 2 + 1] + vbias[vbase + cl + 1];
                }
            }
            __syncthreads();
            int c = tid >> 1, ch = tid & 1;
            uint4 hb[8];
            __half* hbh = (__half*)hb;
            const float* sp = st + c * 132 + ch * 64;
            #pragma unroll
            for (int j = 0; j < 32; j++)
                ((__half2*)hbh)[j] = __floats2half2_rn(sp[2 * j], sp[2 * j + 1]);
            uint4* dp = (uint4*)&C2[sC2 * bz + (size_t)(vbase + c) * NPIX + m0 + ch * 64];
            #pragma unroll
            for (int jj = 0; jj < 8; jj++) dp[jj] = hb[jj];
        }
        return;
    }

    __half* Cp = Ch + sC * bz;
    #pragma unroll
    for (int mt = 0; mt < 2; mt++)
    #pragma unroll
    for (int h = 0; h < 2; h++) {
        int row = m0 + wm + mt * 16 + g + h * 8;
        #pragma unroll
        for (int nt = 0; nt < 8; nt++) {
            int col = n0 + wn + nt * 8 + tg * 2;
            float v0 = acc[mt][nt][h * 2 + 0];
            float v1 = acc[mt][nt][h * 2 + 1];
            if (col < Nall)     { v0 += bias[col];     v0 = v0 > 0.f ? v0 : 0.1f * v0; }
            if (col + 1 < Nall) { v1 += bias[col + 1]; v1 = v1 > 0.f ? v1 : 0.1f * v1; }
            if (col < Nall)
                *(__half2*)&Cp[(size_t)row * ldc + col] = __floats2half2_rn(v0, v1);
        }
    }
}

// ---------------------------------------------------------------------------
// Fused conv2+conv3 (unchanged from R13)
// ---------------------------------------------------------------------------
__global__ void __launch_bounds__(512, 1)
conv23(const __half* __restrict__ A1, const __half* __restrict__ W2,
       const __half* __restrict__ W3, const float* __restrict__ b2,
       const float* __restrict__ b3, __half* __restrict__ A3)
{
    extern __shared__ char smem[];
    uint32_t sb = smem_u32(smem);
    const uint32_t W2o = 0, A1o = 16384, W3o = 32768, A2o = 98304;

    int tid = threadIdx.x, lane = tid & 31, wid = tid >> 5;
    int g = lane >> 2, tg = lane & 3;
    int m0 = blockIdx.x * 128, bz = blockIdx.y;
    const __half* a1B = A1 + ((size_t)bz * NPIX + m0) * 64;

    #pragma unroll
    for (int i = tid; i < 1024; i += 512) {
        int r = i >> 3, c = i & 7;
        CPA16(sb + W2o + r * 128 + ((c ^ (r & 7)) << 4), W2 + r * 64 + c * 8);
    }
    #pragma unroll
    for (int i = tid; i < 1024; i += 512) {
        int r = i >> 3, c = i & 7;
        CPA16(sb + A1o + r * 128 + ((c ^ (r & 7)) << 4), a1B + r * 64 + c * 8);
    }
    #pragma unroll
    for (int i = tid; i < 4096; i += 512) {
        int r = i >> 4, c = i & 15;
        CPA16(sb + W3o + r * 256 + ((c ^ (r & 7)) << 4), W3 + r * 128 + c * 8);
    }
    asm volatile("cp.async.commit_group;\n");
    asm volatile("cp.async.wait_group 0;\n");
    __syncthreads();

    int wm = (wid & 3) * 32;
    int wn1 = (wid >> 2) * 32;
    int wn2 = (wid >> 2) * 64;

    {
        float acc1[2][4][4];
        #pragma unroll
        for (int a = 0; a < 2; a++)
            #pragma unroll
            for (int b = 0; b < 4; b++)
                #pragma unroll
                for (int c = 0; c < 4; c++) acc1[a][b][c] = 0.f;

        #pragma unroll
        for (int ks = 0; ks < 4; ks++) {
            int c0 = ks * 2;
            uint32_t af[2][4];
            #pragma unroll
            for (int mt = 0; mt < 2; mt++) {
                int lr = wm + mt * 16 + (lane & 15);
                int lc = c0 + (lane >> 4);
                LDMX4(af[mt][0], af[mt][1], af[mt][2], af[mt][3],
                      sb + A1o + lr * 128 + ((lc ^ (lr & 7)) << 4));
            }
            uint32_t bf[4][2];
            #pragma unroll
            for (int j = 0; j < 2; j++) {
                int nb_ = wn1 + j * 16;
                int lr = nb_ + (lane & 7) + ((lane >> 4) << 3);
                int lc = c0 + ((lane >> 3) & 1);
                LDMX4(bf[2*j][0], bf[2*j][1], bf[2*j+1][0], bf[2*j+1][1],
                      sb + W2o + lr * 128 + ((lc ^ (lr & 7)) << 4));
            }
            #pragma unroll
            for (int mt = 0; mt < 2; mt++)
                #pragma unroll
                for (int nt = 0; nt < 4; nt++)
                    MMA16816(acc1[mt][nt], af[mt], bf[nt][0], bf[nt][1]);
        }

        #pragma unroll
        for (int mt = 0; mt < 2; mt++)
        #pragma unroll
        for (int h = 0; h < 2; h++) {
            int rl = wm + mt * 16 + g + h * 8;
            #pragma unroll
            for (int nt = 0; nt < 4; nt++) {
                int cl = wn1 + nt * 8 + tg * 2;
                float v0 = acc1[mt][nt][h * 2 + 0] + b2[cl];
                float v1 = acc1[mt][nt][h * 2 + 1] + b2[cl + 1];
                v0 = v0 > 0.f ? v0 : 0.1f * v0;
                v1 = v1 > 0.f ? v1 : 0.1f * v1;
                int u = cl >> 3;
                *(__half2*)(smem + A2o + rl * 256 + ((u ^ (rl & 7)) << 4) + tg * 4)
                    = __floats2half2_rn(v0, v1);
            }
        }
    }
    __syncthreads();

    float acc2[2][8][4];
    #pragma unroll
    for (int a = 0; a < 2; a++)
        #pragma unroll
        for (int b = 0; b < 8; b++)
            #pragma unroll
            for (int c = 0; c < 4; c++) acc2[a][b][c] = 0.f;

    #pragma unroll
    for (int ks = 0; ks < 8; ks++) {
        int c0 = ks * 2;
        uint32_t af2[2][4];
        #pragma unroll
        for (int mt = 0; mt < 2; mt++) {
            int lr = wm + mt * 16 + (lane & 15);
            int lc = c0 + (lane >> 4);
            LDMX4(af2[mt][0], af2[mt][1], af2[mt][2], af2[mt][3],
                  sb + A2o + lr * 256 + ((lc ^ (lr & 7)) << 4));
        }
        uint32_t bf2[8][2];
        #pragma unroll
        for (int j = 0; j < 4; j++) {
            int nb_ = wn2 + j * 16;
            int lr = nb_ + (lane & 7) + ((lane >> 4) << 3);
            int lc = c0 + ((lane >> 3) & 1);
            LDMX4(bf2[2*j][0], bf2[2*j][1], bf2[2*j+1][0], bf2[2*j+1][1],
                  sb + W3o + lr * 256 + ((lc ^ (lr & 7)) << 4));
        }
        #pragma unroll
        for (int mt = 0; mt < 2; mt++)
            #pragma unroll
            for (int nt = 0; nt < 8; nt++)
                MMA16816(acc2[mt][nt], af2[mt], bf2[nt][0], bf2[nt][1]);
    }

    __half* out = A3 + ((size_t)bz * NPIX + m0) * 256;
    #pragma unroll
    for (int mt = 0; mt < 2; mt++)
    #pragma unroll
    for (int h = 0; h < 2; h++) {
        int rl = wm + mt * 16 + g + h * 8;
        #pragma unroll
        for (int nt = 0; nt < 8; nt++) {
            int cl = wn2 + nt * 8 + tg * 2;
            float v0 = acc2[mt][nt][h * 2 + 0] + b3[cl];
            float v1 = acc2[mt][nt][h * 2 + 1] + b3[cl + 1];
            v0 = v0 > 0.f ? v0 : 0.1f * v0;
            v1 = v1 > 0.f ? v1 : 0.1f * v1;
            *(__half2*)&out[(size_t)rl * 256 + cl] = __floats2half2_rn(v0, v1);
        }
    }
}

// ---------------------------------------------------------------------------
// Flash attention — R14: inner barriers are per row-group (warps sharing wmS,
// i.e. wid&3) named barriers. Only the top-of-iter stage barrier is CTA-wide.
// P rows [32g, 32g+32) are written in S and read in PV exclusively by group g.
// ---------------------------------------------------------------------------
#define FSQ 0u
#define FSP 16384u
#define FST 49152u
#define FSTG 81920u
#define FVO 16384u
#define FRB 212992u
#define FRI (FRB + 2048u)
#define FSMEM (FRI + 512u)

template<int CQ>
__global__ void __launch_bounds__(512, 1)
flash(const __half* __restrict__ QK, const __half* __restrict__ V,
      const __half* __restrict__ Res, __half* __restrict__ Out,
      const float* __restrict__ gammaP, int Ctot)
{
    extern __shared__ char smem[];
    uint32_t sb = smem_u32(smem);
    int tid = threadIdx.x, lane = tid & 31, wid = tid >> 5;
    int g = lane >> 2, tg = lane & 3;
    int chunk = blockIdx.x, m0 = blockIdx.y * 128, bz = blockIdx.z;
    const int ldqk = 128;

    const __half* qkB = QK + (size_t)bz * NPIX * ldqk;
    const __half* vB  = V + (size_t)bz * Ctot * NPIX + (size_t)(chunk * 256) * NPIX;

    #pragma unroll
    for (int i = tid; i < 1024; i += 512) {
        int r = i >> 3, u = i & 7;
        uint32_t dst = sb + FSQ + r * 128 + ((u ^ (r & 7)) << 4);
        int ok = (u * 8 < CQ) ? 16 : 0;
        const __half* gp = qkB + (size_t)(m0 + r) * ldqk + u * 8;
        asm volatile("cp.async.cg.shared.global [%0], [%1], 16, %2;\n"
                     :: "r"(dst), "l"(gp), "r"(ok));
    }

    int wmS = (wid & 3) * 32, wnS = (wid >> 2) * 32;
    int wn2 = (wid >> 2) * 64;
    int gbar = (wid & 3) + 1;     // named barrier id for this row-group

    {
        uint32_t kb = sb + FST;
        #pragma unroll
        for (int i = tid; i < 1024; i += 512) {
            int r = i >> 3, u = i & 7;
            uint32_t dst = kb + r * 128 + ((u ^ (r & 7)) << 4);
            int ok = (u * 8 < CQ) ? 16 : 0;
            const __half* gp = qkB + (size_t)r * ldqk + CQ + u * 8;
            asm volatile("cp.async.cg.shared.global [%0], [%1], 16, %2;\n"
                         :: "r"(dst), "l"(gp), "r"(ok));
        }
        uint32_t vb = kb + FVO;
        #pragma unroll
        for (int i = tid; i < 4096; i += 512) {
            int r = i >> 4, u = i & 15;
            uint32_t dst = vb + r * 256 + ((u ^ (r & 7)) << 4);
            const __half* gp = vB + (size_t)r * NPIX + u * 8;
            CPA16(dst, gp);
        }
    }
    asm volatile("cp.async.commit_group;\n");

    float acc2[2][8][4];
    #pragma unroll
    for (int a = 0; a < 2; a++)
        #pragma unroll
        for (int b = 0; b < 8; b++)
            #pragma unroll
            for (int c = 0; c < 4; c++) acc2[a][b][c] = 0.f;
    float rsum[4] = {0.f, 0.f, 0.f, 0.f};

    for (int n = 0; n < 32; n++) {
        asm volatile("cp.async.wait_group 0;\n");
        __syncthreads();                      // CTA-wide: stage buffers ready / drained
        int buf = n & 1;

        if (n + 1 < 32) {
            uint32_t kb = sb + FST + (buf ^ 1) * FSTG;
            int n0 = (n + 1) * 128;
            #pragma unroll
            for (int i = tid; i < 1024; i += 512) {
                int r = i >> 3, u = i & 7;
                uint32_t dst = kb + r * 128 + ((u ^ (r & 7)) << 4);
                int ok = (u * 8 < CQ) ? 16 : 0;
                const __half* gp = qkB + (size_t)(n0 + r) * ldqk + CQ + u * 8;
                asm volatile("cp.async.cg.shared.global [%0], [%1], 16, %2;\n"
                             :: "r"(dst), "l"(gp), "r"(ok));
            }
            uint32_t vb = kb + FVO;
            #pragma unroll
            for (int i = tid; i < 4096; i += 512) {
                int r = i >> 4, u = i & 15;
                uint32_t dst = vb + r * 256 + ((u ^ (r & 7)) << 4);
                const __half* gp = vB + (size_t)r * NPIX + n0 + u * 8;
                CPA16(dst, gp);
            }
        }
        asm volatile("cp.async.commit_group;\n");

        uint32_t kb = sb + FST + buf * FSTG;
        uint32_t vb = kb + FVO;

        #pragma unroll
        for (int mt = 0; mt < 2; mt++) {
            float sa[4][4];
            #pragma unroll
            for (int a = 0; a < 4; a++)
                #pragma unroll
                for (int c = 0; c < 4; c++) sa[a][c] = 0.f;

            #pragma unroll
            for (int ks = 0; ks < CQ / 16; ks++) {
                int c0 = ks * 2;
                uint32_t af[4];
                {
                    int lr = wmS + mt * 16 + (lane & 15);
                    int lc = c0 + (lane >> 4);
                    LDMX4(af[0], af[1], af[2], af[3],
                          sb + FSQ + lr * 128 + ((lc ^ (lr & 7)) << 4));
                }
                uint32_t bf[4][2];
                #pragma unroll
                for (int j = 0; j < 2; j++) {
                    int nb_ = wnS + j * 16;
                    int lr = nb_ + (lane & 7) + ((lane >> 4) << 3);
                    int lc = c0 + ((lane >> 3) & 1);
                    LDMX4(bf[2*j][0], bf[2*j][1], bf[2*j+1][0], bf[2*j+1][1],
                          kb + lr * 128 + ((lc ^ (lr & 7)) << 4));
                }
                #pragma unroll
                for (int nt = 0; nt < 4; nt++)
                    MMA16816(sa[nt], af, bf[nt][0], bf[nt][1]);
            }

            #pragma unroll
            for (int h = 0; h < 2; h++) {
                int rl = wmS + mt * 16 + g + h * 8;
                #pragma unroll
                for (int nt = 0; nt < 4; nt++) {
                    float e0 = __expf(sa[nt][h * 2 + 0] - ESHIFT);
                    float e1 = __expf(sa[nt][h * 2 + 1] - ESHIFT);
                    rsum[mt * 2 + h] += e0 + e1;
                    int u = (wnS >> 3) + nt;
                    *(__half2*)(smem + FSP + rl * 256 + ((u ^ (rl & 7)) << 4) + tg * 4)
                        = __floats2half2_rn(e0, e1);
                }
            }
        }
        GBAR(gbar);                           // group-scoped: P rows ready

        #pragma unroll
        for (int ks = 0; ks < 8; ks++) {
            int c0 = ks * 2;
            uint32_t af2[2][4];
            #pragma unroll
            for (int mt = 0; mt < 2; mt++) {
                int lr = wmS + mt * 16 + (lane & 15);
                int lc = c0 + (lane >> 4);
                LDMX4(af2[mt][0], af2[mt][1], af2[mt][2], af2[mt][3],
                      sb + FSP + lr * 256 + ((lc ^ (lr & 7)) << 4));
            }
            uint32_t bf2[8][2];
            #pragma unroll
            for (int j = 0; j < 4; j++) {
                int nb_ = wn2 + j * 16;
                int lr = nb_ + (lane & 7) + ((lane >> 4) << 3);
                int lc = c0 + ((lane >> 3) & 1);
                LDMX4(bf2[2*j][0], bf2[2*j][1], bf2[2*j+1][0], bf2[2*j+1][1],
                      vb + lr * 256 + ((lc ^ (lr & 7)) << 4));
            }
            #pragma unroll
            for (int mt = 0; mt < 2; mt++)
                #pragma unroll
                for (int nt = 0; nt < 8; nt++)
                    MMA16816(acc2[mt][nt], af2[mt], bf2[nt][0], bf2[nt][1]);
        }
        GBAR(gbar);                           // group-scoped: P consumed, reusable
    }

    #pragma unroll
    for (int i = 0; i < 4; i++) {
        rsum[i] += __shfl_xor_sync(0xffffffffu, rsum[i], 1);
        rsum[i] += __shfl_xor_sync(0xffffffffu, rsum[i], 2);
    }
    float* rbuf = (float*)(smem + FRB);
    if (tg == 0) {
        #pragma unroll
        for (int mt = 0; mt < 2; mt++)
            #pragma unroll
            for (int h = 0; h < 2; h++)
                rbuf[(wid >> 2) * 128 + wmS + mt * 16 + g + h * 8] = rsum[mt * 2 + h];
    }
    __syncthreads();
    float* rinv = (float*)(smem + FRI);
    if (tid < 128) {
        float s = rbuf[tid] + rbuf[128 + tid] + rbuf[256 + tid] + rbuf[384 + tid];
        rinv[tid] = 1.f / s;
    }
    __syncthreads();

    float gam = *gammaP;
    const __half* RB_ = Res + ((size_t)bz * NPIX + m0) * Ctot + chunk * 256;
    __half* OB = Out + ((size_t)bz * NPIX + m0) * Ctot + chunk * 256;
    #pragma unroll
    for (int mt = 0; mt < 2; mt++)
    #pragma unroll
    for (int h = 0; h < 2; h++) {
        int rl = wmS + mt * 16 + g + h * 8;
        float is = gam * rinv[rl];
        #pragma unroll
        for (int nt = 0; nt < 8; nt++) {
            int cl = wn2 + nt * 8 + tg * 2;
            float2 rf = __half22float2(*(const __half2*)&RB_[(size_t)rl * Ctot + cl]);
            float v0 = acc2[mt][nt][h * 2 + 0] * is + rf.x;
            float v1 = acc2[mt][nt][h * 2 + 1] * is + rf.y;
            *(__half2*)&OB[(size_t)rl * Ctot + cl] = __floats2half2_rn(v0, v1);
        }
    }
}

// ---------------------------------------------------------------------------
// fused input transpose + conv1
// ---------------------------------------------------------------------------
__global__ void tin_conv1(const float* __restrict__ in, const float* __restrict__ W1,
                          const float* __restrict__ b1, const float* __restrict__ sig,
                          __half* __restrict__ a1)
{
    __shared__ float ws[64 * 6];
    __shared__ float bs[64];
    int t = threadIdx.x;
    float s = sig[0];
    if (t < 64) bs[t] = b1[t];
    for (int i = t; i < 384; i += 256) ws[i] = W1[i] * s;
    __syncthreads();

    int b = blockIdx.y;
    int p = blockIdx.x * 256 + t;
    const float* x = in + (size_t)b * 6 * NPIX + p;
    float xv[6];
    #pragma unroll
    for (int c = 0; c < 6; c++) xv[c] = x[(size_t)c * NPIX];

    __half ho[64];
    #pragma unroll
    for (int o = 0; o < 64; o++) {
        float acc = bs[o];
        #pragma unroll
        for (int c = 0; c < 6; c++) acc += ws[o * 6 + c] * xv[c];
        acc = acc > 0.f ? acc : 0.1f * acc;
        ho[o] = __float2half(acc);
    }
    uint4* dst = (uint4*)(a1 + ((size_t)b * NPIX + p) * 64);
    #pragma unroll
    for (int i = 0; i < 8; i++) dst[i] = ((uint4*)ho)[i];
}

// ---------------------------------------------------------------------------
// conv5 matvec
// ---------------------------------------------------------------------------
__global__ void conv5_mv(const __half* __restrict__ t2, const float* __restrict__ W5,
                         const float* __restrict__ b5, const float* __restrict__ sig,
                         float* __restrict__ out)
{
    __shared__ float ws[512];
    int t = threadIdx.x, lane = t & 31, w = t >> 5;
    float s = sig[4];
    for (int i = t; i < 512; i += 256) ws[i] = W5[i] * s;
    __syncthreads();

    int r = blockIdx.x * 8 + w;
    const __half* row = t2 + (size_t)r * 512;
    const uint4* rp = (const uint4*)(row + lane * 16);
    float acc = 0.f;
    #pragma unroll
    for (int q = 0; q < 2; q++) {
        uint4 pk = rp[q];
        const __half2* h2 = (const __half2*)&pk;
        #pragma unroll
        for (int j = 0; j < 4; j++) {
            float2 v = __half22float2(h2[j]);
            int c = lane * 16 + q * 8 + j * 2;
            acc += v.x * ws[c] + v.y * ws[c + 1];
        }
    }
    #pragma unroll
    for (int off = 16; off > 0; off >>= 1) acc += __shfl_xor_sync(0xffffffffu, acc, off);
    if (lane == 0) {
        float v = acc + b5[0];
        out[r] = v > 0.f ? v : 0.1f * v;
    }
}

// ---------------------------------------------------------------------------
// spectral norms
// ---------------------------------------------------------------------------
__global__ void snorm_all(const float* __restrict__ W1, const float* __restrict__ u1,
                          const float* __restrict__ W2, const float* __restrict__ u2,
                          const float* __restrict__ W3, const float* __restrict__ u3,
                          const float* __restrict__ W4, const float* __restrict__ u4,
                          const float* __restrict__ W5, const float* __restrict__ u5,
                          float* __restrict__ sig)
{
    __shared__ float vs[512];
    __shared__ float us[512];
    __shared__ float red[256];
    __shared__ float red8[8];

    const float* W; const float* u; int O, C;
    switch (blockIdx.x) {
        case 0: W = W1; u = u1; O = 64;  C = 6;   break;
        case 1: W = W2; u = u2; O = 128; C = 64;  break;
        case 2: W = W3; u = u3; O = 256; C = 128; break;
        case 3: W = W4; u = u4; O = 512; C = 256; break;
        default: W = W5; u = u5; O = 1;  C = 512; break;
    }
    int t = threadIdx.x, lane = t & 31, wid = t >> 5;

    for (int o = t; o < O; o += 256) us[o] = u[o];
    __syncthreads();
    for (int c = t; c < C; c += 256) {
        float s = 0.f;
        #pragma unroll 4
        for (int o = 0; o < O; o++) s += W[(size_t)o * C + c] * us[o];
        vs[c] = s;
    }
    __syncthreads();
    float s = 0.f;
    for (int c = t; c < C; c += 256) s += vs[c] * vs[c];
    red[t] = s; __syncthreads();
    for (int off = 128; off > 0; off >>= 1) { if (t < off) red[t] += red[t + off]; __syncthreads(); }
    float vinv = 1.f / (sqrtf(red[0]) + 1e-12f);
    __syncthreads();
    for (int c = t; c < C; c += 256) vs[c] *= vinv;
    __syncthreads();
    float accq = 0.f;
    for (int o = wid; o < O; o += 8) {
        float tv = 0.f;
        for (int c = lane; c < C; c += 32) tv += W[(size_t)o * C + c] * vs[c];
        #pragma unroll
        for (int off = 16; off > 0; off >>= 1) tv += __shfl_xor_sync(0xffffffffu, tv, off);
        if (lane == 0) accq += tv * tv;
    }
    if (lane == 0) red8[wid] = accq;
    __syncthreads();
    if (t == 0) {
        float S = 0.f;
        #pragma unroll
        for (int w = 0; w < 8; w++) S += red8[w];
        float sigma = S / (sqrtf(S) + 1e-12f);
        sig[blockIdx.x] = 1.f / sigma;
    }
}

// ---------------------------------------------------------------------------
// weight prep
// ---------------------------------------------------------------------------
__global__ void wprep(const float* W2, const float* W3, const float* W4,
                      const float* q1, const float* k1, const float* v1,
                      const float* q2, const float* k2, const float* v2,
                      const float* qb1, const float* kb1,
                      const float* qb2, const float* kb2,
                      const float* sig,
                      __half* o1, __half* o2, __half* o3,
                      __half* qkv1, __half* qkv2,
                      float* d1, float* d2)
{
    if (blockIdx.x == 9) {
        if (blockIdx.y == 0) {
            int t = threadIdx.x;
            if (t < 128) d1[t] = (t < 32) ? qb1[t] : (t < 64 ? kb1[t - 32] : 0.f);
            else { int u = t - 128; d2[u] = (u < 64) ? qb2[u] : kb2[u - 64]; }
        }
        return;
    }
    const float* src; __half* dst; int O, C, Cp; float s = 1.f;
    switch (blockIdx.x) {
        case 0:  src = W2; dst = o1;                O = 128; C = 64;  Cp = 64;  s = sig[1]; break;
        case 1:  src = W3; dst = o2;                O = 256; C = 128; Cp = 128; s = sig[2]; break;
        case 2:  src = W4; dst = o3;                O = 512; C = 256; Cp = 256; s = sig[3]; break;
        case 3:  src = q1; dst = qkv1;              O = 32;  C = 256; Cp = 256; break;
        case 4:  src = k1; dst = qkv1 + 32 * 256;   O = 32;  C = 256; Cp = 256; break;
        case 5:  src = q1; dst = qkv1 + 64 * 256;   O = 64;  C = 0;   Cp = 256; break; // zero pad
        case 6:  src = v1; dst = qkv1 + 128 * 256;  O = 256; C = 256; Cp = 256; break;
        case 7:  src = q2; dst = qkv2;              O = 64;  C = 512; Cp = 512; break;
        case 8:  src = k2; dst = qkv2 + 64 * 512;   O = 64;  C = 512; Cp = 512; break;
        default: src = v2; dst = qkv2 + 128 * 512;  O = 512; C = 512; Cp = 512; break;
    }
    int total = O * Cp;
    for (int i = blockIdx.y * 256 + threadIdx.x; i < total; i += 8 * 256) {
        int o = i / Cp, c = i % Cp;
        float v = (c < C) ? src[(size_t)o * C + c] * s : 0.f;
        dst[i] = __float2half(v);
    }
}

// ---------------------------------------------------------------------------
// kernel_launch
// ---------------------------------------------------------------------------
extern "C" void kernel_launch(void* const* d_in, const int* in_sizes, int n_in,
                              void* d_out, int out_size)
{
    const float* inp  = (const float*)d_in[0];
    const float* W1 = (const float*)d_in[1];  const float* b1 = (const float*)d_in[2];  const float* u1 = (const float*)d_in[3];
    const float* W2 = (const float*)d_in[4];  const float* b2 = (const float*)d_in[5];  const float* u2 = (const float*)d_in[6];
    const float* W3 = (const float*)d_in[7];  const float* b3 = (const float*)d_in[8];  const float* u3 = (const float*)d_in[9];
    const float* W4 = (const float*)d_in[10]; const float* b4 = (const float*)d_in[11]; const float* u4 = (const float*)d_in[12];
    const float* W5 = (const float*)d_in[13]; const float* b5 = (const float*)d_in[14]; const float* u5 = (const float*)d_in[15];
    const float* a1qW = (const float*)d_in[16]; const float* a1qb = (const float*)d_in[17];
    const float* a1kW = (const float*)d_in[18]; const float* a1kb = (const float*)d_in[19];
    const float* a1vW = (const float*)d_in[20]; const float* a1vb = (const float*)d_in[21];
    const float* a1g  = (const float*)d_in[22];
    const float* a2qW = (const float*)d_in[23]; const float* a2qb = (const float*)d_in[24];
    const float* a2kW = (const float*)d_in[25]; const float* a2kb = (const float*)d_in[26];
    const float* a2vW = (const float*)d_in[27]; const float* a2vb = (const float*)d_in[28];
    const float* a2g  = (const float*)d_in[29];

    __half *a1h, *a3h, *qkh, *vh, *t1h, *t2h, *a4h;
    __half *W2h, *W3h, *W4h, *qkv1h, *qkv2h;
    float *sig, *qkb1, *qkb2;
    cudaGetSymbolAddress((void**)&a1h, g_a1);
    cudaGetSymbolAddress((void**)&a3h, g_a3);
    cudaGetSymbolAddress((void**)&qkh, g_qk);
    cudaGetSymbolAddress((void**)&vh,  g_v);
    cudaGetSymbolAddress((void**)&t1h, g_t1);
    cudaGetSymbolAddress((void**)&t2h, g_t2);
    cudaGetSymbolAddress((void**)&a4h, g_a4);
    cudaGetSymbolAddress((void**)&sig, g_sig);
    cudaGetSymbolAddress((void**)&qkb1, g_qkb1);
    cudaGetSymbolAddress((void**)&qkb2, g_qkb2);
    cudaGetSymbolAddress((void**)&W2h, g_W2h);
    cudaGetSymbolAddress((void**)&W3h, g_W3h);
    cudaGetSymbolAddress((void**)&W4h, g_W4h);
    cudaGetSymbolAddress((void**)&qkv1h, g_qkv1h);
    cudaGetSymbolAddress((void**)&qkv2h, g_qkv2h);

    const int SMEMSZ = 98304;
    const int C23SM = 131072;
    cudaFuncSetAttribute(hgemm<0>, cudaFuncAttributeMaxDynamicSharedMemorySize, SMEMSZ);
    cudaFuncSetAttribute(hgemm<7>, cudaFuncAttributeMaxDynamicSharedMemorySize, SMEMSZ);
    cudaFuncSetAttribute(conv23, cudaFuncAttributeMaxDynamicSharedMemorySize, C23SM);
    cudaFuncSetAttribute(flash<32>, cudaFuncAttributeMaxDynamicSharedMemorySize, FSMEM);
    cudaFuncSetAttribute(flash<64>, cudaFuncAttributeMaxDynamicSharedMemorySize, FSMEM);

    const size_t NP = NPIX;
    auto gd = [&](int Nn) { return dim3((Nn + 127) / 128, NPIX / 128, BATCH); };

    snorm_all<<<5, 256>>>(W1, u1, W2, u2, W3, u3, W4, u4, W5, u5, sig);
    wprep<<<dim3(11, 8), 256>>>(W2, W3, W4, a1qW, a1kW, a1vW, a2qW, a2kW, a2vW,
                                a1qb, a1kb, a2qb, a2kb, sig,
                                W2h, W3h, W4h, qkv1h, qkv2h, qkb1, qkb2);

    // fused transpose + conv1
    tin_conv1<<<dim3(16, BATCH), 256>>>(inp, W1, b1, sig, a1h);

    // fused conv2 + conv3
    conv23<<<dim3(32, BATCH), 512, C23SM>>>(a1h, W2h, W3h, b2, b3, a3h);

    // attention 1: merged q|k|v conv (N = 128 qk + 256 v), then flash
    hgemm<7><<<gd(384), 256, SMEMSZ>>>(a3h, qkv1h, qkh, vh, NPIX, 384, 256, 256, 256, 128,
        NP * 256, 0, NP * 128, 256 * NP, 1, qkb1, a1vb);
    flash<32><<<dim3(1, 32, BATCH), 512, FSMEM>>>(qkh, vh, a3h, t1h, a1g, 256);

    // conv4
    hgemm<0><<<gd(512), 256, SMEMSZ>>>(t1h, W4h, a4h, nullptr, NPIX, 512, 256, 256, 256, 512,
        NP * 256, 0, NP * 512, 0, 0, b4, nullptr);

    // attention 2: merged q|k|v conv (N = 128 qk + 512 v), then flash
    hgemm<7><<<gd(640), 256, SMEMSZ>>>(a4h, qkv2h, qkh, vh, NPIX, 640, 512, 512, 512, 128,
        NP * 512, 0, NP * 128, 512 * NP, 1, qkb2, a2vb);
    flash<64><<<dim3(2, 32, BATCH), 512, FSMEM>>>(qkh, vh, a4h, t2h, a2g, 512);

    // conv5 -> f32 output (B, 4096) via warp matvec
    conv5_mv<<<2048, 256>>>(t2h, W5, b5, sig, (float*)d_out);
}

// round 16
// speedup vs baseline: 1.0763x; 1.0763x over previous
#include <cuda_runtime.h>
#include <cuda_fp16.h>
#include <math.h>
#include <stdint.h>

// ---------------------------------------------------------------------------
// SpectralDiscriminator on GB300 — fp16 mma.sync GEMMs + flash-fused attention.
// R16: R13 base (R15 conv4-fusion reverted after correctness failure);
//      conv5 fused into flash2 epilogue (t2 never materialized).
// ---------------------------------------------------------------------------

#define NPIX 4096
#define BATCH 4
#define ESHIFT 4.0f

__device__ __half g_a1 [BATCH * NPIX * 64];
__device__ __half g_a3 [BATCH * NPIX * 256];
__device__ __half g_qk [BATCH * NPIX * 128];          // [pix][128]: q|k (+pad for attn1)
__device__ __half g_v  [BATCH * 512 * NPIX];          // channel-major [c][pix]
__device__ __half g_t1 [BATCH * NPIX * 256];
__device__ __half g_a4 [BATCH * NPIX * 512];
__device__ float g_p5 [2 * BATCH * NPIX];             // conv5 partials per chunk
__device__ float g_sig[8];
__device__ float g_qkb1[128];
__device__ float g_qkb2[128];
__device__ __half g_W2h[128 * 64];
__device__ __half g_W3h[256 * 128];
__device__ __half g_W4h[512 * 256];
__device__ __half g_qkv1h[384 * 256];   // [q32|k32|pad64|v256] x 256
__device__ __half g_qkv2h[640 * 512];   // [q64|k64|v512] x 512

__device__ __forceinline__ uint32_t smem_u32(const void* p) {
    uint32_t a;
    asm("{ .reg .u64 t; cvta.to.shared.u64 t, %1; cvt.u32.u64 %0, t; }" : "=r"(a) : "l"(p));
    return a;
}

#define LDMX4(r0, r1, r2, r3, ad) \
    asm volatile("ldmatrix.sync.aligned.m8n8.x4.shared.b16 {%0,%1,%2,%3}, [%4];\n" \
        : "=r"(r0), "=r"(r1), "=r"(r2), "=r"(r3) : "r"(ad))

#define MMA16816(d, a, b0, b1) \
    asm volatile("mma.sync.aligned.m16n8k16.row.col.f32.f16.f16.f32 " \
        "{%0,%1,%2,%3}, {%4,%5,%6,%7}, {%8,%9}, {%0,%1,%2,%3};\n" \
        : "+f"((d)[0]), "+f"((d)[1]), "+f"((d)[2]), "+f"((d)[3]) \
        : "r"((a)[0]), "r"((a)[1]), "r"((a)[2]), "r"((a)[3]), "r"(b0), "r"(b1))

#define CPA16(dst, src) \
    asm volatile("cp.async.cg.shared.global [%0], [%1], 16;\n" :: "r"(dst), "l"(src))

// cp.async one 128-row x 64-half tile into SW128 smem (128B rows)
__device__ __forceinline__ void cpa_tile(uint32_t dstBase, const __half* src, int ld,
                                         int Rall, int r0, int K, int k0, int tid) {
    #pragma unroll
    for (int i = 0; i < 4; i++) {
        int e = tid + i * 256;
        int r = e >> 3, c = e & 7;
        int gr = r0 + r;
        uint32_t dst = dstBase + r * 128 + ((c ^ (r & 7)) << 4);
        bool ok = (gr < Rall) && (k0 + c * 8 < K);
        const __half* g = src + (ok ? ((size_t)gr * ld + k0 + c * 8) : 0);
        int bytes = ok ? 16 : 0;
        asm volatile("cp.async.cg.shared.global [%0], [%1], 16, %2;\n"
                     :: "r"(dst), "l"(g), "r"(bytes));
    }
}

// ---------------------------------------------------------------------------
// fp16 GEMM: C[m][n] = sum_k A[m,k]*B[n,k]. x = n-tile (fast), y = m-tile.
// EPI: 0 leaky(acc+bias[n]) -> fp16
//      7 merged qkv: blockIdx.x < qkTiles -> acc+bias[n] plain to Ch (ldc);
//                    else -> acc+vbias transposed to C2[(n-128)*NPIX+m] via bounce
// ---------------------------------------------------------------------------
template<int EPI>
__global__ void __launch_bounds__(256, 2)
hgemm(const __half* __restrict__ A, const __half* __restrict__ B,
      __half* __restrict__ Ch, __half* __restrict__ C2,
      int Mall, int Nall, int K, int lda, int ldb, int ldc,
      size_t sA, size_t sB, size_t sC, size_t sC2, int qkTiles,
      const float* __restrict__ bias, const float* __restrict__ vbias)
{
    extern __shared__ char smem[];
    uint32_t sbase = smem_u32(smem);
    const uint32_t stageSz = 32768;

    int tid = threadIdx.x, lane = tid & 31, wid = tid >> 5;
    int bz = blockIdx.z;
    A += sA * bz;  B += sB * bz;

    int m0 = blockIdx.y * 128;
    int n0 = blockIdx.x * 128;
    int wm = (wid & 3) * 32;
    int wn = (wid >> 2) * 64;

    float acc[2][8][4];
    #pragma unroll
    for (int a = 0; a < 2; a++)
        #pragma unroll
        for (int b = 0; b < 8; b++)
            #pragma unroll
            for (int c = 0; c < 4; c++) acc[a][b][c] = 0.f;

    int nkt = (K + 63) >> 6;

    #pragma unroll
    for (int s = 0; s < 2; s++) {
        if (s < nkt) {
            uint32_t b = sbase + s * stageSz;
            cpa_tile(b, A, lda, Mall, m0, K, s * 64, tid);
            cpa_tile(b + 16384, B, ldb, Nall, n0, K, s * 64, tid);
        }
        asm volatile("cp.async.commit_group;\n");
    }

    for (int kt = 0; kt < nkt; kt++) {
        asm volatile("cp.async.wait_group 1;\n");
        __syncthreads();

        uint32_t Ab = sbase + (kt % 3) * stageSz;
        uint32_t Bb = Ab + 16384;

        int kl = K - kt * 64;
        int nks = (kl >= 64) ? 4 : ((kl + 15) >> 4);

        #pragma unroll 4
        for (int ks = 0; ks < nks; ks++) {
            int c0 = ks * 2;
            uint32_t af[2][4];
            #pragma unroll
            for (int mt = 0; mt < 2; mt++) {
                int lr = wm + mt * 16 + (lane & 15);
                int lc = c0 + (lane >> 4);
                LDMX4(af[mt][0], af[mt][1], af[mt][2], af[mt][3],
                      Ab + lr * 128 + ((lc ^ (lr & 7)) << 4));
            }
            uint32_t bf[8][2];
            #pragma unroll
            for (int j = 0; j < 4; j++) {
                int nb_ = wn + j * 16;
                int lr = nb_ + (lane & 7) + ((lane >> 4) << 3);
                int lc = c0 + ((lane >> 3) & 1);
                LDMX4(bf[2*j][0], bf[2*j][1], bf[2*j+1][0], bf[2*j+1][1],
                      Bb + lr * 128 + ((lc ^ (lr & 7)) << 4));
            }
            #pragma unroll
            for (int mt = 0; mt < 2; mt++)
                #pragma unroll
                for (int nt = 0; nt < 8; nt++)
                    MMA16816(acc[mt][nt], af[mt], bf[nt][0], bf[nt][1]);
        }

        int nx = kt + 2;
        if (nx < nkt) {
            uint32_t b = sbase + (nx % 3) * stageSz;
            cpa_tile(b, A, lda, Mall, m0, K, nx * 64, tid);
            cpa_tile(b + 16384, B, ldb, Nall, n0, K, nx * 64, tid);
        }
        asm volatile("cp.async.commit_group;\n");
    }

    int g = lane >> 2, tg = lane & 3;

    if (EPI == 7) {
        if ((int)blockIdx.x < qkTiles) {
            __half* Cp = Ch + sC * bz;
            #pragma unroll
            for (int mt = 0; mt < 2; mt++)
            #pragma unroll
            for (int h = 0; h < 2; h++) {
                int row = m0 + wm + mt * 16 + g + h * 8;
                #pragma unroll
                for (int nt = 0; nt < 8; nt++) {
                    int col = n0 + wn + nt * 8 + tg * 2;
                    float v0 = acc[mt][nt][h * 2 + 0] + bias[col];
                    float v1 = acc[mt][nt][h * 2 + 1] + bias[col + 1];
                    *(__half2*)&Cp[(size_t)row * ldc + col] = __floats2half2_rn(v0, v1);
                }
            }
        } else {
            int vbase = n0 - qkTiles * 128;
            asm volatile("cp.async.wait_group 0;\n");
            __syncthreads();
            float* st = (float*)smem;
            #pragma unroll
            for (int mt = 0; mt < 2; mt++)
            #pragma unroll
            for (int h = 0; h < 2; h++) {
                int rl = wm + mt * 16 + g + h * 8;
                #pragma unroll
                for (int nt = 0; nt < 8; nt++) {
                    int cl = wn + nt * 8 + tg * 2;
                    st[cl * 132 + rl]       = acc[mt][nt][h * 2 + 0] + vbias[vbase + cl];
                    st[(cl + 1) * 132 + rl] = acc[mt][nt][h * 2 + 1] + vbias[vbase + cl + 1];
                }
            }
            __syncthreads();
            int c = tid >> 1, ch = tid & 1;
            uint4 hb[8];
            __half* hbh = (__half*)hb;
            const float* sp = st + c * 132 + ch * 64;
            #pragma unroll
            for (int j = 0; j < 32; j++)
                ((__half2*)hbh)[j] = __floats2half2_rn(sp[2 * j], sp[2 * j + 1]);
            uint4* dp = (uint4*)&C2[sC2 * bz + (size_t)(vbase + c) * NPIX + m0 + ch * 64];
            #pragma unroll
            for (int jj = 0; jj < 8; jj++) dp[jj] = hb[jj];
        }
        return;
    }

    __half* Cp = Ch + sC * bz;
    #pragma unroll
    for (int mt = 0; mt < 2; mt++)
    #pragma unroll
    for (int h = 0; h < 2; h++) {
        int row = m0 + wm + mt * 16 + g + h * 8;
        #pragma unroll
        for (int nt = 0; nt < 8; nt++) {
            int col = n0 + wn + nt * 8 + tg * 2;
            float v0 = acc[mt][nt][h * 2 + 0];
            float v1 = acc[mt][nt][h * 2 + 1];
            if (col < Nall)     { v0 += bias[col];     v0 = v0 > 0.f ? v0 : 0.1f * v0; }
            if (col + 1 < Nall) { v1 += bias[col + 1]; v1 = v1 > 0.f ? v1 : 0.1f * v1; }
            if (col < Nall)
                *(__half2*)&Cp[(size_t)row * ldc + col] = __floats2half2_rn(v0, v1);
        }
    }
}

// ---------------------------------------------------------------------------
// Fused conv2+conv3 (unchanged from R13)
// ---------------------------------------------------------------------------
__global__ void __launch_bounds__(512, 1)
conv23(const __half* __restrict__ A1, const __half* __restrict__ W2,
       const __half* __restrict__ W3, const float* __restrict__ b2,
       const float* __restrict__ b3, __half* __restrict__ A3)
{
    extern __shared__ char smem[];
    uint32_t sb = smem_u32(smem);
    const uint32_t W2o = 0, A1o = 16384, W3o = 32768, A2o = 98304;

    int tid = threadIdx.x, lane = tid & 31, wid = tid >> 5;
    int g = lane >> 2, tg = lane & 3;
    int m0 = blockIdx.x * 128, bz = blockIdx.y;
    const __half* a1B = A1 + ((size_t)bz * NPIX + m0) * 64;

    #pragma unroll
    for (int i = tid; i < 1024; i += 512) {
        int r = i >> 3, c = i & 7;
        CPA16(sb + W2o + r * 128 + ((c ^ (r & 7)) << 4), W2 + r * 64 + c * 8);
    }
    #pragma unroll
    for (int i = tid; i < 1024; i += 512) {
        int r = i >> 3, c = i & 7;
        CPA16(sb + A1o + r * 128 + ((c ^ (r & 7)) << 4), a1B + r * 64 + c * 8);
    }
    #pragma unroll
    for (int i = tid; i < 4096; i += 512) {
        int r = i >> 4, c = i & 15;
        CPA16(sb + W3o + r * 256 + ((c ^ (r & 7)) << 4), W3 + r * 128 + c * 8);
    }
    asm volatile("cp.async.commit_group;\n");
    asm volatile("cp.async.wait_group 0;\n");
    __syncthreads();

    int wm = (wid & 3) * 32;
    int wn1 = (wid >> 2) * 32;
    int wn2 = (wid >> 2) * 64;

    {
        float acc1[2][4][4];
        #pragma unroll
        for (int a = 0; a < 2; a++)
            #pragma unroll
            for (int b = 0; b < 4; b++)
                #pragma unroll
                for (int c = 0; c < 4; c++) acc1[a][b][c] = 0.f;

        #pragma unroll
        for (int ks = 0; ks < 4; ks++) {
            int c0 = ks * 2;
            uint32_t af[2][4];
            #pragma unroll
            for (int mt = 0; mt < 2; mt++) {
                int lr = wm + mt * 16 + (lane & 15);
                int lc = c0 + (lane >> 4);
                LDMX4(af[mt][0], af[mt][1], af[mt][2], af[mt][3],
                      sb + A1o + lr * 128 + ((lc ^ (lr & 7)) << 4));
            }
            uint32_t bf[4][2];
            #pragma unroll
            for (int j = 0; j < 2; j++) {
                int nb_ = wn1 + j * 16;
                int lr = nb_ + (lane & 7) + ((lane >> 4) << 3);
                int lc = c0 + ((lane >> 3) & 1);
                LDMX4(bf[2*j][0], bf[2*j][1], bf[2*j+1][0], bf[2*j+1][1],
                      sb + W2o + lr * 128 + ((lc ^ (lr & 7)) << 4));
            }
            #pragma unroll
            for (int mt = 0; mt < 2; mt++)
                #pragma unroll
                for (int nt = 0; nt < 4; nt++)
                    MMA16816(acc1[mt][nt], af[mt], bf[nt][0], bf[nt][1]);
        }

        #pragma unroll
        for (int mt = 0; mt < 2; mt++)
        #pragma unroll
        for (int h = 0; h < 2; h++) {
            int rl = wm + mt * 16 + g + h * 8;
            #pragma unroll
            for (int nt = 0; nt < 4; nt++) {
                int cl = wn1 + nt * 8 + tg * 2;
                float v0 = acc1[mt][nt][h * 2 + 0] + b2[cl];
                float v1 = acc1[mt][nt][h * 2 + 1] + b2[cl + 1];
                v0 = v0 > 0.f ? v0 : 0.1f * v0;
                v1 = v1 > 0.f ? v1 : 0.1f * v1;
                int u = cl >> 3;
                *(__half2*)(smem + A2o + rl * 256 + ((u ^ (rl & 7)) << 4) + tg * 4)
                    = __floats2half2_rn(v0, v1);
            }
        }
    }
    __syncthreads();

    float acc2[2][8][4];
    #pragma unroll
    for (int a = 0; a < 2; a++)
        #pragma unroll
        for (int b = 0; b < 8; b++)
            #pragma unroll
            for (int c = 0; c < 4; c++) acc2[a][b][c] = 0.f;

    #pragma unroll
    for (int ks = 0; ks < 8; ks++) {
        int c0 = ks * 2;
        uint32_t af2[2][4];
        #pragma unroll
        for (int mt = 0; mt < 2; mt++) {
            int lr = wm + mt * 16 + (lane & 15);
            int lc = c0 + (lane >> 4);
            LDMX4(af2[mt][0], af2[mt][1], af2[mt][2], af2[mt][3],
                  sb + A2o + lr * 256 + ((lc ^ (lr & 7)) << 4));
        }
        uint32_t bf2[8][2];
        #pragma unroll
        for (int j = 0; j < 4; j++) {
            int nb_ = wn2 + j * 16;
            int lr = nb_ + (lane & 7) + ((lane >> 4) << 3);
            int lc = c0 + ((lane >> 3) & 1);
            LDMX4(bf2[2*j][0], bf2[2*j][1], bf2[2*j+1][0], bf2[2*j+1][1],
                  sb + W3o + lr * 256 + ((lc ^ (lr & 7)) << 4));
        }
        #pragma unroll
        for (int mt = 0; mt < 2; mt++)
            #pragma unroll
            for (int nt = 0; nt < 8; nt++)
                MMA16816(acc2[mt][nt], af2[mt], bf2[nt][0], bf2[nt][1]);
    }

    __half* out = A3 + ((size_t)bz * NPIX + m0) * 256;
    #pragma unroll
    for (int mt = 0; mt < 2; mt++)
    #pragma unroll
    for (int h = 0; h < 2; h++) {
        int rl = wm + mt * 16 + g + h * 8;
        #pragma unroll
        for (int nt = 0; nt < 8; nt++) {
            int cl = wn2 + nt * 8 + tg * 2;
            float v0 = acc2[mt][nt][h * 2 + 0] + b3[cl];
            float v1 = acc2[mt][nt][h * 2 + 1] + b3[cl + 1];
            v0 = v0 > 0.f ? v0 : 0.1f * v0;
            v1 = v1 > 0.f ? v1 : 0.1f * v1;
            *(__half2*)&out[(size_t)rl * 256 + cl] = __floats2half2_rn(v0, v1);
        }
    }
}

// ---------------------------------------------------------------------------
// Flash attention. FUSE5=0: write Out (gamma*acc*rinv + Res) as fp16.
// FUSE5=1: skip Out; accumulate conv5 partial dot (w5 scaled by sig[4]) and
// write one f32 partial per (chunk, pixel) to P5. Main loop identical to R13.
// ---------------------------------------------------------------------------
#define FSQ 0u
#define FSP 16384u
#define FST 49152u
#define FSTG 81920u
#define FVO 16384u
#define FRB 212992u
#define FRI (FRB + 2048u)
#define W5S (FRI + 512u)
#define FSMEM (W5S + 1024u)

template<int CQ, int FUSE5>
__global__ void __launch_bounds__(512, 1)
flash(const __half* __restrict__ QK, const __half* __restrict__ V,
      const __half* __restrict__ Res, __half* __restrict__ Out,
      const float* __restrict__ gammaP, int Ctot,
      const float* __restrict__ W5, const float* __restrict__ sigp,
      float* __restrict__ P5)
{
    extern __shared__ char smem[];
    uint32_t sb = smem_u32(smem);
    int tid = threadIdx.x, lane = tid & 31, wid = tid >> 5;
    int g = lane >> 2, tg = lane & 3;
    int chunk = blockIdx.x, m0 = blockIdx.y * 128, bz = blockIdx.z;
    const int ldqk = 128;

    const __half* qkB = QK + (size_t)bz * NPIX * ldqk;
    const __half* vB  = V + (size_t)bz * Ctot * NPIX + (size_t)(chunk * 256) * NPIX;

    if (FUSE5) {
        float* w5s = (float*)(smem + W5S);
        if (tid < 256) w5s[tid] = W5[chunk * 256 + tid] * sigp[4];
    }

    #pragma unroll
    for (int i = tid; i < 1024; i += 512) {
        int r = i >> 3, u = i & 7;
        uint32_t dst = sb + FSQ + r * 128 + ((u ^ (r & 7)) << 4);
        int ok = (u * 8 < CQ) ? 16 : 0;
        const __half* gp = qkB + (size_t)(m0 + r) * ldqk + u * 8;
        asm volatile("cp.async.cg.shared.global [%0], [%1], 16, %2;\n"
                     :: "r"(dst), "l"(gp), "r"(ok));
    }

    int wmS = (wid & 3) * 32, wnS = (wid >> 2) * 32;
    int wn2 = (wid >> 2) * 64;

    {
        uint32_t kb = sb + FST;
        #pragma unroll
        for (int i = tid; i < 1024; i += 512) {
            int r = i >> 3, u = i & 7;
            uint32_t dst = kb + r * 128 + ((u ^ (r & 7)) << 4);
            int ok = (u * 8 < CQ) ? 16 : 0;
            const __half* gp = qkB + (size_t)r * ldqk + CQ + u * 8;
            asm volatile("cp.async.cg.shared.global [%0], [%1], 16, %2;\n"
                         :: "r"(dst), "l"(gp), "r"(ok));
        }
        uint32_t vb = kb + FVO;
        #pragma unroll
        for (int i = tid; i < 4096; i += 512) {
            int r = i >> 4, u = i & 15;
            uint32_t dst = vb + r * 256 + ((u ^ (r & 7)) << 4);
            const __half* gp = vB + (size_t)r * NPIX + u * 8;
            CPA16(dst, gp);
        }
    }
    asm volatile("cp.async.commit_group;\n");

    float acc2[2][8][4];
    #pragma unroll
    for (int a = 0; a < 2; a++)
        #pragma unroll
        for (int b = 0; b < 8; b++)
            #pragma unroll
            for (int c = 0; c < 4; c++) acc2[a][b][c] = 0.f;
    float rsum[4] = {0.f, 0.f, 0.f, 0.f};

    for (int n = 0; n < 32; n++) {
        asm volatile("cp.async.wait_group 0;\n");
        __syncthreads();
        int buf = n & 1;

        if (n + 1 < 32) {
            uint32_t kb = sb + FST + (buf ^ 1) * FSTG;
            int n0 = (n + 1) * 128;
            #pragma unroll
            for (int i = tid; i < 1024; i += 512) {
                int r = i >> 3, u = i & 7;
                uint32_t dst = kb + r * 128 + ((u ^ (r & 7)) << 4);
                int ok = (u * 8 < CQ) ? 16 : 0;
                const __half* gp = qkB + (size_t)(n0 + r) * ldqk + CQ + u * 8;
                asm volatile("cp.async.cg.shared.global [%0], [%1], 16, %2;\n"
                             :: "r"(dst), "l"(gp), "r"(ok));
            }
            uint32_t vb = kb + FVO;
            #pragma unroll
            for (int i = tid; i < 4096; i += 512) {
                int r = i >> 4, u = i & 15;
                uint32_t dst = vb + r * 256 + ((u ^ (r & 7)) << 4);
                const __half* gp = vB + (size_t)r * NPIX + n0 + u * 8;
                CPA16(dst, gp);
            }
        }
        asm volatile("cp.async.commit_group;\n");

        uint32_t kb = sb + FST + buf * FSTG;
        uint32_t vb = kb + FVO;

        #pragma unroll
        for (int mt = 0; mt < 2; mt++) {
            float sa[4][4];
            #pragma unroll
            for (int a = 0; a < 4; a++)
                #pragma unroll
                for (int c = 0; c < 4; c++) sa[a][c] = 0.f;

            #pragma unroll
            for (int ks = 0; ks < CQ / 16; ks++) {
                int c0 = ks * 2;
                uint32_t af[4];
                {
                    int lr = wmS + mt * 16 + (lane & 15);
                    int lc = c0 + (lane >> 4);
                    LDMX4(af[0], af[1], af[2], af[3],
                          sb + FSQ + lr * 128 + ((lc ^ (lr & 7)) << 4));
                }
                uint32_t bf[4][2];
                #pragma unroll
                for (int j = 0; j < 2; j++) {
                    int nb_ = wnS + j * 16;
                    int lr = nb_ + (lane & 7) + ((lane >> 4) << 3);
                    int lc = c0 + ((lane >> 3) & 1);
                    LDMX4(bf[2*j][0], bf[2*j][1], bf[2*j+1][0], bf[2*j+1][1],
                          kb + lr * 128 + ((lc ^ (lr & 7)) << 4));
                }
                #pragma unroll
                for (int nt = 0; nt < 4; nt++)
                    MMA16816(sa[nt], af, bf[nt][0], bf[nt][1]);
            }

            #pragma unroll
            for (int h = 0; h < 2; h++) {
                int rl = wmS + mt * 16 + g + h * 8;
                #pragma unroll
                for (int nt = 0; nt < 4; nt++) {
                    float e0 = __expf(sa[nt][h * 2 + 0] - ESHIFT);
                    float e1 = __expf(sa[nt][h * 2 + 1] - ESHIFT);
                    rsum[mt * 2 + h] += e0 + e1;
                    int u = (wnS >> 3) + nt;
                    *(__half2*)(smem + FSP + rl * 256 + ((u ^ (rl & 7)) << 4) + tg * 4)
                        = __floats2half2_rn(e0, e1);
                }
            }
        }
        __syncthreads();

        #pragma unroll
        for (int ks = 0; ks < 8; ks++) {
            int c0 = ks * 2;
            uint32_t af2[2][4];
            #pragma unroll
            for (int mt = 0; mt < 2; mt++) {
                int lr = wmS + mt * 16 + (lane & 15);
                int lc = c0 + (lane >> 4);
                LDMX4(af2[mt][0], af2[mt][1], af2[mt][2], af2[mt][3],
                      sb + FSP + lr * 256 + ((lc ^ (lr & 7)) << 4));
            }
            uint32_t bf2[8][2];
            #pragma unroll
            for (int j = 0; j < 4; j++) {
                int nb_ = wn2 + j * 16;
                int lr = nb_ + (lane & 7) + ((lane >> 4) << 3);
                int lc = c0 + ((lane >> 3) & 1);
                LDMX4(bf2[2*j][0], bf2[2*j][1], bf2[2*j+1][0], bf2[2*j+1][1],
                      vb + lr * 256 + ((lc ^ (lr & 7)) << 4));
            }
            #pragma unroll
            for (int mt = 0; mt < 2; mt++)
                #pragma unroll
                for (int nt = 0; nt < 8; nt++)
                    MMA16816(acc2[mt][nt], af2[mt], bf2[nt][0], bf2[nt][1]);
        }
        __syncthreads();
    }

    // ---- rowsum -> rinv (unchanged)
    #pragma unroll
    for (int i = 0; i < 4; i++) {
        rsum[i] += __shfl_xor_sync(0xffffffffu, rsum[i], 1);
        rsum[i] += __shfl_xor_sync(0xffffffffu, rsum[i], 2);
    }
    float* rbuf = (float*)(smem + FRB);
    if (tg == 0) {
        #pragma unroll
        for (int mt = 0; mt < 2; mt++)
            #pragma unroll
            for (int h = 0; h < 2; h++)
                rbuf[(wid >> 2) * 128 + wmS + mt * 16 + g + h * 8] = rsum[mt * 2 + h];
    }
    __syncthreads();
    float* rinv = (float*)(smem + FRI);
    if (tid < 128) {
        float s = rbuf[tid] + rbuf[128 + tid] + rbuf[256 + tid] + rbuf[384 + tid];
        rinv[tid] = 1.f / s;
    }
    __syncthreads();

    float gam = *gammaP;
    const __half* RB_ = Res + ((size_t)bz * NPIX + m0) * Ctot + chunk * 256;
    __half* OB = Out + ((size_t)bz * NPIX + m0) * Ctot + chunk * 256;
    float* w5s = (float*)(smem + W5S);
    float part[4] = {0.f, 0.f, 0.f, 0.f};

    #pragma unroll
    for (int mt = 0; mt < 2; mt++)
    #pragma unroll
    for (int h = 0; h < 2; h++) {
        int rl = wmS + mt * 16 + g + h * 8;
        float is = gam * rinv[rl];
        #pragma unroll
        for (int nt = 0; nt < 8; nt++) {
            int cl = wn2 + nt * 8 + tg * 2;
            float2 rf = __half22float2(*(const __half2*)&RB_[(size_t)rl * Ctot + cl]);
            float v0 = acc2[mt][nt][h * 2 + 0] * is + rf.x;
            float v1 = acc2[mt][nt][h * 2 + 1] * is + rf.y;
            if (FUSE5) {
                part[mt * 2 + h] += v0 * w5s[cl] + v1 * w5s[cl + 1];
            } else {
                *(__half2*)&OB[(size_t)rl * Ctot + cl] = __floats2half2_rn(v0, v1);
            }
        }
    }

    if (FUSE5) {
        // reduce conv5 partials: tg lanes, then the 4 warps sharing each row
        #pragma unroll
        for (int i = 0; i < 4; i++) {
            part[i] += __shfl_xor_sync(0xffffffffu, part[i], 1);
            part[i] += __shfl_xor_sync(0xffffffffu, part[i], 2);
        }
        if (tg == 0) {
            #pragma unroll
            for (int mt = 0; mt < 2; mt++)
                #pragma unroll
                for (int h = 0; h < 2; h++)
                    rbuf[(wid >> 2) * 128 + wmS + mt * 16 + g + h * 8] = part[mt * 2 + h];
        }
        __syncthreads();
        if (tid < 128) {
            float s = rbuf[tid] + rbuf[128 + tid] + rbuf[256 + tid] + rbuf[384 + tid];
            P5[(size_t)chunk * (BATCH * NPIX) + (size_t)bz * NPIX + m0 + tid] = s;
        }
    }
}

// ---------------------------------------------------------------------------
// conv5 finalize: out[r] = leaky(p5[0][r] + p5[1][r] + b5)
// ---------------------------------------------------------------------------
__global__ void conv5_fin(const float* __restrict__ p5, const float* __restrict__ b5,
                          float* __restrict__ out)
{
    int r = blockIdx.x * 256 + threadIdx.x;
    float v = p5[r] + p5[BATCH * NPIX + r] + b5[0];
    out[r] = v > 0.f ? v : 0.1f * v;
}

// ---------------------------------------------------------------------------
// fused input transpose + conv1
// ---------------------------------------------------------------------------
__global__ void tin_conv1(const float* __restrict__ in, const float* __restrict__ W1,
                          const float* __restrict__ b1, const float* __restrict__ sig,
                          __half* __restrict__ a1)
{
    __shared__ float ws[64 * 6];
    __shared__ float bs[64];
    int t = threadIdx.x;
    float s = sig[0];
    if (t < 64) bs[t] = b1[t];
    for (int i = t; i < 384; i += 256) ws[i] = W1[i] * s;
    __syncthreads();

    int b = blockIdx.y;
    int p = blockIdx.x * 256 + t;
    const float* x = in + (size_t)b * 6 * NPIX + p;
    float xv[6];
    #pragma unroll
    for (int c = 0; c < 6; c++) xv[c] = x[(size_t)c * NPIX];

    __half ho[64];
    #pragma unroll
    for (int o = 0; o < 64; o++) {
        float acc = bs[o];
        #pragma unroll
        for (int c = 0; c < 6; c++) acc += ws[o * 6 + c] * xv[c];
        acc = acc > 0.f ? acc : 0.1f * acc;
        ho[o] = __float2half(acc);
    }
    uint4* dst = (uint4*)(a1 + ((size_t)b * NPIX + p) * 64);
    #pragma unroll
    for (int i = 0; i < 8; i++) dst[i] = ((uint4*)ho)[i];
}

// ---------------------------------------------------------------------------
// spectral norms
// ---------------------------------------------------------------------------
__global__ void snorm_all(const float* __restrict__ W1, const float* __restrict__ u1,
                          const float* __restrict__ W2, const float* __restrict__ u2,
                          const float* __restrict__ W3, const float* __restrict__ u3,
                          const float* __restrict__ W4, const float* __restrict__ u4,
                          const float* __restrict__ W5, const float* __restrict__ u5,
                          float* __restrict__ sig)
{
    __shared__ float vs[512];
    __shared__ float us[512];
    __shared__ float red[256];
    __shared__ float red8[8];

    const float* W; const float* u; int O, C;
    switch (blockIdx.x) {
        case 0: W = W1; u = u1; O = 64;  C = 6;   break;
        case 1: W = W2; u = u2; O = 128; C = 64;  break;
        case 2: W = W3; u = u3; O = 256; C = 128; break;
        case 3: W = W4; u = u4; O = 512; C = 256; break;
        default: W = W5; u = u5; O = 1;  C = 512; break;
    }
    int t = threadIdx.x, lane = t & 31, wid = t >> 5;

    for (int o = t; o < O; o += 256) us[o] = u[o];
    __syncthreads();
    for (int c = t; c < C; c += 256) {
        float s = 0.f;
        #pragma unroll 4
        for (int o = 0; o < O; o++) s += W[(size_t)o * C + c] * us[o];
        vs[c] = s;
    }
    __syncthreads();
    float s = 0.f;
    for (int c = t; c < C; c += 256) s += vs[c] * vs[c];
    red[t] = s; __syncthreads();
    for (int off = 128; off > 0; off >>= 1) { if (t < off) red[t] += red[t + off]; __syncthreads(); }
    float vinv = 1.f / (sqrtf(red[0]) + 1e-12f);
    __syncthreads();
    for (int c = t; c < C; c += 256) vs[c] *= vinv;
    __syncthreads();
    float accq = 0.f;
    for (int o = wid; o < O; o += 8) {
        float tv = 0.f;
        for (int c = lane; c < C; c += 32) tv += W[(size_t)o * C + c] * vs[c];
        #pragma unroll
        for (int off = 16; off > 0; off >>= 1) tv += __shfl_xor_sync(0xffffffffu, tv, off);
        if (lane == 0) accq += tv * tv;
    }
    if (lane == 0) red8[wid] = accq;
    __syncthreads();
    if (t == 0) {
        float S = 0.f;
        #pragma unroll
        for (int w = 0; w < 8; w++) S += red8[w];
        float sigma = S / (sqrtf(S) + 1e-12f);
        sig[blockIdx.x] = 1.f / sigma;
    }
}

// ---------------------------------------------------------------------------
// weight prep
// ---------------------------------------------------------------------------
__global__ void wprep(const float* W2, const float* W3, const float* W4,
                      const float* q1, const float* k1, const float* v1,
                      const float* q2, const float* k2, const float* v2,
                      const float* qb1, const float* kb1,
                      const float* qb2, const float* kb2,
                      const float* sig,
                      __half* o1, __half* o2, __half* o3,
                      __half* qkv1, __half* qkv2,
                      float* d1, float* d2)
{
    if (blockIdx.x == 9) {
        if (blockIdx.y == 0) {
            int t = threadIdx.x;
            if (t < 128) d1[t] = (t < 32) ? qb1[t] : (t < 64 ? kb1[t - 32] : 0.f);
            else { int u = t - 128; d2[u] = (u < 64) ? qb2[u] : kb2[u - 64]; }
        }
        return;
    }
    const float* src; __half* dst; int O, C, Cp; float s = 1.f;
    switch (blockIdx.x) {
        case 0:  src = W2; dst = o1;                O = 128; C = 64;  Cp = 64;  s = sig[1]; break;
        case 1:  src = W3; dst = o2;                O = 256; C = 128; Cp = 128; s = sig[2]; break;
        case 2:  src = W4; dst = o3;                O = 512; C = 256; Cp = 256; s = sig[3]; break;
        case 3:  src = q1; dst = qkv1;              O = 32;  C = 256; Cp = 256; break;
        case 4:  src = k1; dst = qkv1 + 32 * 256;   O = 32;  C = 256; Cp = 256; break;
        case 5:  src = q1; dst = qkv1 + 64 * 256;   O = 64;  C = 0;   Cp = 256; break; // zero pad
        case 6:  src = v1; dst = qkv1 + 128 * 256;  O = 256; C = 256; Cp = 256; break;
        case 7:  src = q2; dst = qkv2;              O = 64;  C = 512; Cp = 512; break;
        case 8:  src = k2; dst = qkv2 + 64 * 512;   O = 64;  C = 512; Cp = 512; break;
        default: src = v2; dst = qkv2 + 128 * 512;  O = 512; C = 512; Cp = 512; break;
    }
    int total = O * Cp;
    for (int i = blockIdx.y * 256 + threadIdx.x; i < total; i += 8 * 256) {
        int o = i / Cp, c = i % Cp;
        float v = (c < C) ? src[(size_t)o * C + c] * s : 0.f;
        dst[i] = __float2half(v);
    }
}

// ---------------------------------------------------------------------------
// kernel_launch
// ---------------------------------------------------------------------------
extern "C" void kernel_launch(void* const* d_in, const int* in_sizes, int n_in,
                              void* d_out, int out_size)
{
    const float* inp  = (const float*)d_in[0];
    const float* W1 = (const float*)d_in[1];  const float* b1 = (const float*)d_in[2];  const float* u1 = (const float*)d_in[3];
    const float* W2 = (const float*)d_in[4];  const float* b2 = (const float*)d_in[5];  const float* u2 = (const float*)d_in[6];
    const float* W3 = (const float*)d_in[7];  const float* b3 = (const float*)d_in[8];  const float* u3 = (const float*)d_in[9];
    const float* W4 = (const float*)d_in[10]; const float* b4 = (const float*)d_in[11]; const float* u4 = (const float*)d_in[12];
    const float* W5 = (const float*)d_in[13]; const float* b5 = (const float*)d_in[14]; const float* u5 = (const float*)d_in[15];
    const float* a1qW = (const float*)d_in[16]; const float* a1qb = (const float*)d_in[17];
    const float* a1kW = (const float*)d_in[18]; const float* a1kb = (const float*)d_in[19];
    const float* a1vW = (const float*)d_in[20]; const float* a1vb = (const float*)d_in[21];
    const float* a1g  = (const float*)d_in[22];
    const float* a2qW = (const float*)d_in[23]; const float* a2qb = (const float*)d_in[24];
    const float* a2kW = (const float*)d_in[25]; const float* a2kb = (const float*)d_in[26];
    const float* a2vW = (const float*)d_in[27]; const float* a2vb = (const float*)d_in[28];
    const float* a2g  = (const float*)d_in[29];

    __half *a1h, *a3h, *qkh, *vh, *t1h, *a4h;
    __half *W2h, *W3h, *W4h, *qkv1h, *qkv2h;
    float *sig, *qkb1, *qkb2, *p5;
    cudaGetSymbolAddress((void**)&a1h, g_a1);
    cudaGetSymbolAddress((void**)&a3h, g_a3);
    cudaGetSymbolAddress((void**)&qkh, g_qk);
    cudaGetSymbolAddress((void**)&vh,  g_v);
    cudaGetSymbolAddress((void**)&t1h, g_t1);
    cudaGetSymbolAddress((void**)&a4h, g_a4);
    cudaGetSymbolAddress((void**)&p5,  g_p5);
    cudaGetSymbolAddress((void**)&sig, g_sig);
    cudaGetSymbolAddress((void**)&qkb1, g_qkb1);
    cudaGetSymbolAddress((void**)&qkb2, g_qkb2);
    cudaGetSymbolAddress((void**)&W2h, g_W2h);
    cudaGetSymbolAddress((void**)&W3h, g_W3h);
    cudaGetSymbolAddress((void**)&W4h, g_W4h);
    cudaGetSymbolAddress((void**)&qkv1h, g_qkv1h);
    cudaGetSymbolAddress((void**)&qkv2h, g_qkv2h);

    const int SMEMSZ = 98304;
    const int C23SM = 131072;
    cudaFuncSetAttribute(hgemm<0>, cudaFuncAttributeMaxDynamicSharedMemorySize, SMEMSZ);
    cudaFuncSetAttribute(hgemm<7>, cudaFuncAttributeMaxDynamicSharedMemorySize, SMEMSZ);
    cudaFuncSetAttribute(conv23, cudaFuncAttributeMaxDynamicSharedMemorySize, C23SM);
    cudaFuncSetAttribute((const void*)flash<32,0>, cudaFuncAttributeMaxDynamicSharedMemorySize, FSMEM);
    cudaFuncSetAttribute((const void*)flash<64,1>, cudaFuncAttributeMaxDynamicSharedMemorySize, FSMEM);

    const size_t NP = NPIX;
    auto gd = [&](int Nn) { return dim3((Nn + 127) / 128, NPIX / 128, BATCH); };

    snorm_all<<<5, 256>>>(W1, u1, W2, u2, W3, u3, W4, u4, W5, u5, sig);
    wprep<<<dim3(11, 8), 256>>>(W2, W3, W4, a1qW, a1kW, a1vW, a2qW, a2kW, a2vW,
                                a1qb, a1kb, a2qb, a2kb, sig,
                                W2h, W3h, W4h, qkv1h, qkv2h, qkb1, qkb2);

    // fused transpose + conv1
    tin_conv1<<<dim3(16, BATCH), 256>>>(inp, W1, b1, sig, a1h);

    // fused conv2 + conv3
    conv23<<<dim3(32, BATCH), 512, C23SM>>>(a1h, W2h, W3h, b2, b3, a3h);

    // attention 1: merged q|k|v conv (N = 128 qk + 256 v), then flash -> t1
    hgemm<7><<<gd(384), 256, SMEMSZ>>>(a3h, qkv1h, qkh, vh, NPIX, 384, 256, 256, 256, 128,
        NP * 256, 0, NP * 128, 256 * NP, 1, qkb1, a1vb);
    flash<32,0><<<dim3(1, 32, BATCH), 512, FSMEM>>>(qkh, vh, a3h, t1h, a1g, 256,
        nullptr, nullptr, nullptr);

    // conv4
    hgemm<0><<<gd(512), 256, SMEMSZ>>>(t1h, W4h, a4h, nullptr, NPIX, 512, 256, 256, 256, 512,
        NP * 256, 0, NP * 512, 0, 0, b4, nullptr);

    // attention 2: merged q|k|v conv, then flash with fused conv5 partials
    hgemm<7><<<gd(640), 256, SMEMSZ>>>(a4h, qkv2h, qkh, vh, NPIX, 640, 512, 512, 512, 128,
        NP * 512, 0, NP * 128, 512 * NP, 1, qkb2, a2vb);
    flash<64,1><<<dim3(2, 32, BATCH), 512, FSMEM>>>(qkh, vh, a4h, nullptr, a2g, 512,
        W5, sig, p5);

    // conv5 finalize -> f32 output (B, 4096)
    conv5_fin<<<BATCH * NPIX / 256, 256>>>(p5, b5, (float*)d_out);
}

// round 17
// speedup vs baseline: 1.0933x; 1.0158x over previous
#include <cuda_runtime.h>
#include <cuda_fp16.h>
#include <math.h>
#include <stdint.h>

// ---------------------------------------------------------------------------
// SpectralDiscriminator on GB300 — fp16 mma.sync GEMMs + flash-fused attention.
// R17: softmax exp via ex2.approx.f16x2 (one MUFU per pair, halves the
//      S-phase MUFU bottleneck); conv5 stays fused in flash2 epilogue.
// ---------------------------------------------------------------------------

#define NPIX 4096
#define BATCH 4

__device__ __half g_a1 [BATCH * NPIX * 64];
__device__ __half g_a3 [BATCH * NPIX * 256];
__device__ __half g_qk [BATCH * NPIX * 128];          // [pix][128]: q|k (+pad for attn1)
__device__ __half g_v  [BATCH * 512 * NPIX];          // channel-major [c][pix]
__device__ __half g_t1 [BATCH * NPIX * 256];
__device__ __half g_a4 [BATCH * NPIX * 512];
__device__ float g_p5 [2 * BATCH * NPIX];             // conv5 partials per chunk
__device__ float g_sig[8];
__device__ float g_qkb1[128];
__device__ float g_qkb2[128];
__device__ __half g_W2h[128 * 64];
__device__ __half g_W3h[256 * 128];
__device__ __half g_W4h[512 * 256];
__device__ __half g_qkv1h[384 * 256];   // [q32|k32|pad64|v256] x 256
__device__ __half g_qkv2h[640 * 512];   // [q64|k64|v512] x 512

__device__ __forceinline__ uint32_t smem_u32(const void* p) {
    uint32_t a;
    asm("{ .reg .u64 t; cvta.to.shared.u64 t, %1; cvt.u32.u64 %0, t; }" : "=r"(a) : "l"(p));
    return a;
}

#define LDMX4(r0, r1, r2, r3, ad) \
    asm volatile("ldmatrix.sync.aligned.m8n8.x4.shared.b16 {%0,%1,%2,%3}, [%4];\n" \
        : "=r"(r0), "=r"(r1), "=r"(r2), "=r"(r3) : "r"(ad))

#define MMA16816(d, a, b0, b1) \
    asm volatile("mma.sync.aligned.m16n8k16.row.col.f32.f16.f16.f32 " \
        "{%0,%1,%2,%3}, {%4,%5,%6,%7}, {%8,%9}, {%0,%1,%2,%3};\n" \
        : "+f"((d)[0]), "+f"((d)[1]), "+f"((d)[2]), "+f"((d)[3]) \
        : "r"((a)[0]), "r"((a)[1]), "r"((a)[2]), "r"((a)[3]), "r"(b0), "r"(b1))

#define CPA16(dst, src) \
    asm volatile("cp.async.cg.shared.global [%0], [%1], 16;\n" :: "r"(dst), "l"(src))

// cp.async one 128-row x 64-half tile into SW128 smem (128B rows)
__device__ __forceinline__ void cpa_tile(uint32_t dstBase, const __half* src, int ld,
                                         int Rall, int r0, int K, int k0, int tid) {
    #pragma unroll
    for (int i = 0; i < 4; i++) {
        int e = tid + i * 256;
        int r = e >> 3, c = e & 7;
        int gr = r0 + r;
        uint32_t dst = dstBase + r * 128 + ((c ^ (r & 7)) << 4);
        bool ok = (gr < Rall) && (k0 + c * 8 < K);
        const __half* g = src + (ok ? ((size_t)gr * ld + k0 + c * 8) : 0);
        int bytes = ok ? 16 : 0;
        asm volatile("cp.async.cg.shared.global [%0], [%1], 16, %2;\n"
                     :: "r"(dst), "l"(g), "r"(bytes));
    }
}

// ---------------------------------------------------------------------------
// fp16 GEMM: C[m][n] = sum_k A[m,k]*B[n,k]. x = n-tile (fast), y = m-tile.
// EPI: 0 leaky(acc+bias[n]) -> fp16
//      7 merged qkv: blockIdx.x < qkTiles -> acc+bias[n] plain to Ch (ldc);
//                    else -> acc+vbias transposed to C2[(n-128)*NPIX+m] via bounce
// ---------------------------------------------------------------------------
template<int EPI>
__global__ void __launch_bounds__(256, 2)
hgemm(const __half* __restrict__ A, const __half* __restrict__ B,
      __half* __restrict__ Ch, __half* __restrict__ C2,
      int Mall, int Nall, int K, int lda, int ldb, int ldc,
      size_t sA, size_t sB, size_t sC, size_t sC2, int qkTiles,
      const float* __restrict__ bias, const float* __restrict__ vbias)
{
    extern __shared__ char smem[];
    uint32_t sbase = smem_u32(smem);
    const uint32_t stageSz = 32768;

    int tid = threadIdx.x, lane = tid & 31, wid = tid >> 5;
    int bz = blockIdx.z;
    A += sA * bz;  B += sB * bz;

    int m0 = blockIdx.y * 128;
    int n0 = blockIdx.x * 128;
    int wm = (wid & 3) * 32;
    int wn = (wid >> 2) * 64;

    float acc[2][8][4];
    #pragma unroll
    for (int a = 0; a < 2; a++)
        #pragma unroll
        for (int b = 0; b < 8; b++)
            #pragma unroll
            for (int c = 0; c < 4; c++) acc[a][b][c] = 0.f;

    int nkt = (K + 63) >> 6;

    #pragma unroll
    for (int s = 0; s < 2; s++) {
        if (s < nkt) {
            uint32_t b = sbase + s * stageSz;
            cpa_tile(b, A, lda, Mall, m0, K, s * 64, tid);
            cpa_tile(b + 16384, B, ldb, Nall, n0, K, s * 64, tid);
        }
        asm volatile("cp.async.commit_group;\n");
    }

    for (int kt = 0; kt < nkt; kt++) {
        asm volatile("cp.async.wait_group 1;\n");
        __syncthreads();

        uint32_t Ab = sbase + (kt % 3) * stageSz;
        uint32_t Bb = Ab + 16384;

        int kl = K - kt * 64;
        int nks = (kl >= 64) ? 4 : ((kl + 15) >> 4);

        #pragma unroll 4
        for (int ks = 0; ks < nks; ks++) {
            int c0 = ks * 2;
            uint32_t af[2][4];
            #pragma unroll
            for (int mt = 0; mt < 2; mt++) {
                int lr = wm + mt * 16 + (lane & 15);
                int lc = c0 + (lane >> 4);
                LDMX4(af[mt][0], af[mt][1], af[mt][2], af[mt][3],
                      Ab + lr * 128 + ((lc ^ (lr & 7)) << 4));
            }
            uint32_t bf[8][2];
            #pragma unroll
            for (int j = 0; j < 4; j++) {
                int nb_ = wn + j * 16;
                int lr = nb_ + (lane & 7) + ((lane >> 4) << 3);
                int lc = c0 + ((lane >> 3) & 1);
                LDMX4(bf[2*j][0], bf[2*j][1], bf[2*j+1][0], bf[2*j+1][1],
                      Bb + lr * 128 + ((lc ^ (lr & 7)) << 4));
            }
            #pragma unroll
            for (int mt = 0; mt < 2; mt++)
                #pragma unroll
                for (int nt = 0; nt < 8; nt++)
                    MMA16816(acc[mt][nt], af[mt], bf[nt][0], bf[nt][1]);
        }

        int nx = kt + 2;
        if (nx < nkt) {
            uint32_t b = sbase + (nx % 3) * stageSz;
            cpa_tile(b, A, lda, Mall, m0, K, nx * 64, tid);
            cpa_tile(b + 16384, B, ldb, Nall, n0, K, nx * 64, tid);
        }
        asm volatile("cp.async.commit_group;\n");
    }

    int g = lane >> 2, tg = lane & 3;

    if (EPI == 7) {
        if ((int)blockIdx.x < qkTiles) {
            __half* Cp = Ch + sC * bz;
            #pragma unroll
            for (int mt = 0; mt < 2; mt++)
            #pragma unroll
            for (int h = 0; h < 2; h++) {
                int row = m0 + wm + mt * 16 + g + h * 8;
                #pragma unroll
                for (int nt = 0; nt < 8; nt++) {
                    int col = n0 + wn + nt * 8 + tg * 2;
                    float v0 = acc[mt][nt][h * 2 + 0] + bias[col];
                    float v1 = acc[mt][nt][h * 2 + 1] + bias[col + 1];
                    *(__half2*)&Cp[(size_t)row * ldc + col] = __floats2half2_rn(v0, v1);
                }
            }
        } else {
            int vbase = n0 - qkTiles * 128;
            asm volatile("cp.async.wait_group 0;\n");
            __syncthreads();
            float* st = (float*)smem;
            #pragma unroll
            for (int mt = 0; mt < 2; mt++)
            #pragma unroll
            for (int h = 0; h < 2; h++) {
                int rl = wm + mt * 16 + g + h * 8;
                #pragma unroll
                for (int nt = 0; nt < 8; nt++) {
                    int cl = wn + nt * 8 + tg * 2;
                    st[cl * 132 + rl]       = acc[mt][nt][h * 2 + 0] + vbias[vbase + cl];
                    st[(cl + 1) * 132 + rl] = acc[mt][nt][h * 2 + 1] + vbias[vbase + cl + 1];
                }
            }
            __syncthreads();
            int c = tid >> 1, ch = tid & 1;
            uint4 hb[8];
            __half* hbh = (__half*)hb;
            const float* sp = st + c * 132 + ch * 64;
            #pragma unroll
            for (int j = 0; j < 32; j++)
                ((__half2*)hbh)[j] = __floats2half2_rn(sp[2 * j], sp[2 * j + 1]);
            uint4* dp = (uint4*)&C2[sC2 * bz + (size_t)(vbase + c) * NPIX + m0 + ch * 64];
            #pragma unroll
            for (int jj = 0; jj < 8; jj++) dp[jj] = hb[jj];
        }
        return;
    }

    __half* Cp = Ch + sC * bz;
    #pragma unroll
    for (int mt = 0; mt < 2; mt++)
    #pragma unroll
    for (int h = 0; h < 2; h++) {
        int row = m0 + wm + mt * 16 + g + h * 8;
        #pragma unroll
        for (int nt = 0; nt < 8; nt++) {
            int col = n0 + wn + nt * 8 + tg * 2;
            float v0 = acc[mt][nt][h * 2 + 0];
            float v1 = acc[mt][nt][h * 2 + 1];
            if (col < Nall)     { v0 += bias[col];     v0 = v0 > 0.f ? v0 : 0.1f * v0; }
            if (col + 1 < Nall) { v1 += bias[col + 1]; v1 = v1 > 0.f ? v1 : 0.1f * v1; }
            if (col < Nall)
                *(__half2*)&Cp[(size_t)row * ldc + col] = __floats2half2_rn(v0, v1);
        }
    }
}

// ---------------------------------------------------------------------------
// Fused conv2+conv3 (unchanged)
// ---------------------------------------------------------------------------
__global__ void __launch_bounds__(512, 1)
conv23(const __half* __restrict__ A1, const __half* __restrict__ W2,
       const __half* __restrict__ W3, const float* __restrict__ b2,
       const float* __restrict__ b3, __half* __restrict__ A3)
{
    extern __shared__ char smem[];
    uint32_t sb = smem_u32(smem);
    const uint32_t W2o = 0, A1o = 16384, W3o = 32768, A2o = 98304;

    int tid = threadIdx.x, lane = tid & 31, wid = tid >> 5;
    int g = lane >> 2, tg = lane & 3;
    int m0 = blockIdx.x * 128, bz = blockIdx.y;
    const __half* a1B = A1 + ((size_t)bz * NPIX + m0) * 64;

    #pragma unroll
    for (int i = tid; i < 1024; i += 512) {
        int r = i >> 3, c = i & 7;
        CPA16(sb + W2o + r * 128 + ((c ^ (r & 7)) << 4), W2 + r * 64 + c * 8);
    }
    #pragma unroll
    for (int i = tid; i < 1024; i += 512) {
        int r = i >> 3, c = i & 7;
        CPA16(sb + A1o + r * 128 + ((c ^ (r & 7)) << 4), a1B + r * 64 + c * 8);
    }
    #pragma unroll
    for (int i = tid; i < 4096; i += 512) {
        int r = i >> 4, c = i & 15;
        CPA16(sb + W3o + r * 256 + ((c ^ (r & 7)) << 4), W3 + r * 128 + c * 8);
    }
    asm volatile("cp.async.commit_group;\n");
    asm volatile("cp.async.wait_group 0;\n");
    __syncthreads();

    int wm = (wid & 3) * 32;
    int wn1 = (wid >> 2) * 32;
    int wn2 = (wid >> 2) * 64;

    {
        float acc1[2][4][4];
        #pragma unroll
        for (int a = 0; a < 2; a++)
            #pragma unroll
            for (int b = 0; b < 4; b++)
                #pragma unroll
                for (int c = 0; c < 4; c++) acc1[a][b][c] = 0.f;

        #pragma unroll
        for (int ks = 0; ks < 4; ks++) {
            int c0 = ks * 2;
            uint32_t af[2][4];
            #pragma unroll
            for (int mt = 0; mt < 2; mt++) {
                int lr = wm + mt * 16 + (lane & 15);
                int lc = c0 + (lane >> 4);
                LDMX4(af[mt][0], af[mt][1], af[mt][2], af[mt][3],
                      sb + A1o + lr * 128 + ((lc ^ (lr & 7)) << 4));
            }
            uint32_t bf[4][2];
            #pragma unroll
            for (int j = 0; j < 2; j++) {
                int nb_ = wn1 + j * 16;
                int lr = nb_ + (lane & 7) + ((lane >> 4) << 3);
                int lc = c0 + ((lane >> 3) & 1);
                LDMX4(bf[2*j][0], bf[2*j][1], bf[2*j+1][0], bf[2*j+1][1],
                      sb + W2o + lr * 128 + ((lc ^ (lr & 7)) << 4));
            }
            #pragma unroll
            for (int mt = 0; mt < 2; mt++)
                #pragma unroll
                for (int nt = 0; nt < 4; nt++)
                    MMA16816(acc1[mt][nt], af[mt], bf[nt][0], bf[nt][1]);
        }

        #pragma unroll
        for (int mt = 0; mt < 2; mt++)
        #pragma unroll
        for (int h = 0; h < 2; h++) {
            int rl = wm + mt * 16 + g + h * 8;
            #pragma unroll
            for (int nt = 0; nt < 4; nt++) {
                int cl = wn1 + nt * 8 + tg * 2;
                float v0 = acc1[mt][nt][h * 2 + 0] + b2[cl];
                float v1 = acc1[mt][nt][h * 2 + 1] + b2[cl + 1];
                v0 = v0 > 0.f ? v0 : 0.1f * v0;
                v1 = v1 > 0.f ? v1 : 0.1f * v1;
                int u = cl >> 3;
                *(__half2*)(smem + A2o + rl * 256 + ((u ^ (rl & 7)) << 4) + tg * 4)
                    = __floats2half2_rn(v0, v1);
            }
        }
    }
    __syncthreads();

    float acc2[2][8][4];
    #pragma unroll
    for (int a = 0; a < 2; a++)
        #pragma unroll
        for (int b = 0; b < 8; b++)
            #pragma unroll
            for (int c = 0; c < 4; c++) acc2[a][b][c] = 0.f;

    #pragma unroll
    for (int ks = 0; ks < 8; ks++) {
        int c0 = ks * 2;
        uint32_t af2[2][4];
        #pragma unroll
        for (int mt = 0; mt < 2; mt++) {
            int lr = wm + mt * 16 + (lane & 15);
            int lc = c0 + (lane >> 4);
            LDMX4(af2[mt][0], af2[mt][1], af2[mt][2], af2[mt][3],
                  sb + A2o + lr * 256 + ((lc ^ (lr & 7)) << 4));
        }
        uint32_t bf2[8][2];
        #pragma unroll
        for (int j = 0; j < 4; j++) {
            int nb_ = wn2 + j * 16;
            int lr = nb_ + (lane & 7) + ((lane >> 4) << 3);
            int lc = c0 + ((lane >> 3) & 1);
            LDMX4(bf2[2*j][0], bf2[2*j][1], bf2[2*j+1][0], bf2[2*j+1][1],
                  sb + W3o + lr * 256 + ((lc ^ (lr & 7)) << 4));
        }
        #pragma unroll
        for (int mt = 0; mt < 2; mt++)
            #pragma unroll
            for (int nt = 0; nt < 8; nt++)
                MMA16816(acc2[mt][nt], af2[mt], bf2[nt][0], bf2[nt][1]);
    }

    __half* out = A3 + ((size_t)bz * NPIX + m0) * 256;
    #pragma unroll
    for (int mt = 0; mt < 2; mt++)
    #pragma unroll
    for (int h = 0; h < 2; h++) {
        int rl = wm + mt * 16 + g + h * 8;
        #pragma unroll
        for (int nt = 0; nt < 8; nt++) {
            int cl = wn2 + nt * 8 + tg * 2;
            float v0 = acc2[mt][nt][h * 2 + 0] + b3[cl];
            float v1 = acc2[mt][nt][h * 2 + 1] + b3[cl + 1];
            v0 = v0 > 0.f ? v0 : 0.1f * v0;
            v1 = v1 > 0.f ? v1 : 0.1f * v1;
            *(__half2*)&out[(size_t)rl * 256 + cl] = __floats2half2_rn(v0, v1);
        }
    }
}

// ---------------------------------------------------------------------------
// Flash attention. FUSE5=0: write Out (gamma*acc*rinv + Res) fp16.
// FUSE5=1: accumulate conv5 partial dot instead; write f32 partial to P5.
// exp(s-4) computed as ex2.approx.f16x2 of (s*log2e - 4*log2e).
// ---------------------------------------------------------------------------
#define FSQ 0u
#define FSP 16384u
#define FST 49152u
#define FSTG 81920u
#define FVO 16384u
#define FRB 212992u
#define FRI (FRB + 2048u)
#define W5S (FRI + 512u)
#define FSMEM (W5S + 1024u)
#define L2E 1.44269504f
#define SH2 5.77078016f

template<int CQ, int FUSE5>
__global__ void __launch_bounds__(512, 1)
flash(const __half* __restrict__ QK, const __half* __restrict__ V,
      const __half* __restrict__ Res, __half* __restrict__ Out,
      const float* __restrict__ gammaP, int Ctot,
      const float* __restrict__ W5, const float* __restrict__ sigp,
      float* __restrict__ P5)
{
    extern __shared__ char smem[];
    uint32_t sb = smem_u32(smem);
    int tid = threadIdx.x, lane = tid & 31, wid = tid >> 5;
    int g = lane >> 2, tg = lane & 3;
    int chunk = blockIdx.x, m0 = blockIdx.y * 128, bz = blockIdx.z;
    const int ldqk = 128;

    const __half* qkB = QK + (size_t)bz * NPIX * ldqk;
    const __half* vB  = V + (size_t)bz * Ctot * NPIX + (size_t)(chunk * 256) * NPIX;

    if (FUSE5) {
        float* w5s = (float*)(smem + W5S);
        if (tid < 256) w5s[tid] = W5[chunk * 256 + tid] * sigp[4];
    }

    #pragma unroll
    for (int i = tid; i < 1024; i += 512) {
        int r = i >> 3, u = i & 7;
        uint32_t dst = sb + FSQ + r * 128 + ((u ^ (r & 7)) << 4);
        int ok = (u * 8 < CQ) ? 16 : 0;
        const __half* gp = qkB + (size_t)(m0 + r) * ldqk + u * 8;
        asm volatile("cp.async.cg.shared.global [%0], [%1], 16, %2;\n"
                     :: "r"(dst), "l"(gp), "r"(ok));
    }

    int wmS = (wid & 3) * 32, wnS = (wid >> 2) * 32;
    int wn2 = (wid >> 2) * 64;

    {
        uint32_t kb = sb + FST;
        #pragma unroll
        for (int i = tid; i < 1024; i += 512) {
            int r = i >> 3, u = i & 7;
            uint32_t dst = kb + r * 128 + ((u ^ (r & 7)) << 4);
            int ok = (u * 8 < CQ) ? 16 : 0;
            const __half* gp = qkB + (size_t)r * ldqk + CQ + u * 8;
            asm volatile("cp.async.cg.shared.global [%0], [%1], 16, %2;\n"
                         :: "r"(dst), "l"(gp), "r"(ok));
        }
        uint32_t vb = kb + FVO;
        #pragma unroll
        for (int i = tid; i < 4096; i += 512) {
            int r = i >> 4, u = i & 15;
            uint32_t dst = vb + r * 256 + ((u ^ (r & 7)) << 4);
            const __half* gp = vB + (size_t)r * NPIX + u * 8;
            CPA16(dst, gp);
        }
    }
    asm volatile("cp.async.commit_group;\n");

    float acc2[2][8][4];
    #pragma unroll
    for (int a = 0; a < 2; a++)
        #pragma unroll
        for (int b = 0; b < 8; b++)
            #pragma unroll
            for (int c = 0; c < 4; c++) acc2[a][b][c] = 0.f;
    float rsum[4] = {0.f, 0.f, 0.f, 0.f};

    for (int n = 0; n < 32; n++) {
        asm volatile("cp.async.wait_group 0;\n");
        __syncthreads();
        int buf = n & 1;

        if (n + 1 < 32) {
            uint32_t kb = sb + FST + (buf ^ 1) * FSTG;
            int n0 = (n + 1) * 128;
            #pragma unroll
            for (int i = tid; i < 1024; i += 512) {
                int r = i >> 3, u = i & 7;
                uint32_t dst = kb + r * 128 + ((u ^ (r & 7)) << 4);
                int ok = (u * 8 < CQ) ? 16 : 0;
                const __half* gp = qkB + (size_t)(n0 + r) * ldqk + CQ + u * 8;
                asm volatile("cp.async.cg.shared.global [%0], [%1], 16, %2;\n"
                             :: "r"(dst), "l"(gp), "r"(ok));
            }
            uint32_t vb = kb + FVO;
            #pragma unroll
            for (int i = tid; i < 4096; i += 512) {
                int r = i >> 4, u = i & 15;
                uint32_t dst = vb + r * 256 + ((u ^ (r & 7)) << 4);
                const __half* gp = vB + (size_t)r * NPIX + n0 + u * 8;
                CPA16(dst, gp);
            }
        }
        asm volatile("cp.async.commit_group;\n");

        uint32_t kb = sb + FST + buf * FSTG;
        uint32_t vb = kb + FVO;

        #pragma unroll
        for (int mt = 0; mt < 2; mt++) {
            float sa[4][4];
            #pragma unroll
            for (int a = 0; a < 4; a++)
                #pragma unroll
                for (int c = 0; c < 4; c++) sa[a][c] = 0.f;

            #pragma unroll
            for (int ks = 0; ks < CQ / 16; ks++) {
                int c0 = ks * 2;
                uint32_t af[4];
                {
                    int lr = wmS + mt * 16 + (lane & 15);
                    int lc = c0 + (lane >> 4);
                    LDMX4(af[0], af[1], af[2], af[3],
                          sb + FSQ + lr * 128 + ((lc ^ (lr & 7)) << 4));
                }
                uint32_t bf[4][2];
                #pragma unroll
                for (int j = 0; j < 2; j++) {
                    int nb_ = wnS + j * 16;
                    int lr = nb_ + (lane & 7) + ((lane >> 4) << 3);
                    int lc = c0 + ((lane >> 3) & 1);
                    LDMX4(bf[2*j][0], bf[2*j][1], bf[2*j+1][0], bf[2*j+1][1],
                          kb + lr * 128 + ((lc ^ (lr & 7)) << 4));
                }
                #pragma unroll
                for (int nt = 0; nt < 4; nt++)
                    MMA16816(sa[nt], af, bf[nt][0], bf[nt][1]);
            }

            #pragma unroll
            for (int h = 0; h < 2; h++) {
                int rl = wmS + mt * 16 + g + h * 8;
                #pragma unroll
                for (int nt = 0; nt < 4; nt++) {
                    float x0 = sa[nt][h * 2 + 0] * L2E - SH2;
                    float x1 = sa[nt][h * 2 + 1] * L2E - SH2;
                    uint32_t xp, ep;
                    asm("cvt.rn.f16x2.f32 %0, %1, %2;\n" : "=r"(xp) : "f"(x1), "f"(x0));
                    asm("ex2.approx.f16x2 %0, %1;\n" : "=r"(ep) : "r"(xp));
                    float2 ef = __half22float2(*(__half2*)&ep);
                    rsum[mt * 2 + h] += ef.x + ef.y;
                    int u = (wnS >> 3) + nt;
                    *(uint32_t*)(smem + FSP + rl * 256 + ((u ^ (rl & 7)) << 4) + tg * 4) = ep;
                }
            }
        }
        __syncthreads();

        #pragma unroll
        for (int ks = 0; ks < 8; ks++) {
            int c0 = ks * 2;
            uint32_t af2[2][4];
            #pragma unroll
            for (int mt = 0; mt < 2; mt++) {
                int lr = wmS + mt * 16 + (lane & 15);
                int lc = c0 + (lane >> 4);
                LDMX4(af2[mt][0], af2[mt][1], af2[mt][2], af2[mt][3],
                      sb + FSP + lr * 256 + ((lc ^ (lr & 7)) << 4));
            }
            uint32_t bf2[8][2];
            #pragma unroll
            for (int j = 0; j < 4; j++) {
                int nb_ = wn2 + j * 16;
                int lr = nb_ + (lane & 7) + ((lane >> 4) << 3);
                int lc = c0 + ((lane >> 3) & 1);
                LDMX4(bf2[2*j][0], bf2[2*j][1], bf2[2*j+1][0], bf2[2*j+1][1],
                      vb + lr * 256 + ((lc ^ (lr & 7)) << 4));
            }
            #pragma unroll
            for (int mt = 0; mt < 2; mt++)
                #pragma unroll
                for (int nt = 0; nt < 8; nt++)
                    MMA16816(acc2[mt][nt], af2[mt], bf2[nt][0], bf2[nt][1]);
        }
        __syncthreads();
    }

    // ---- rowsum -> rinv
    #pragma unroll
    for (int i = 0; i < 4; i++) {
        rsum[i] += __shfl_xor_sync(0xffffffffu, rsum[i], 1);
        rsum[i] += __shfl_xor_sync(0xffffffffu, rsum[i], 2);
    }
    float* rbuf = (float*)(smem + FRB);
    if (tg == 0) {
        #pragma unroll
        for (int mt = 0; mt < 2; mt++)
            #pragma unroll
            for (int h = 0; h < 2; h++)
                rbuf[(wid >> 2) * 128 + wmS + mt * 16 + g + h * 8] = rsum[mt * 2 + h];
    }
    __syncthreads();
    float* rinv = (float*)(smem + FRI);
    if (tid < 128) {
        float s = rbuf[tid] + rbuf[128 + tid] + rbuf[256 + tid] + rbuf[384 + tid];
        rinv[tid] = 1.f / s;
    }
    __syncthreads();

    float gam = *gammaP;
    const __half* RB_ = Res + ((size_t)bz * NPIX + m0) * Ctot + chunk * 256;
    __half* OB = Out + ((size_t)bz * NPIX + m0) * Ctot + chunk * 256;
    float* w5s = (float*)(smem + W5S);
    float part[4] = {0.f, 0.f, 0.f, 0.f};

    #pragma unroll
    for (int mt = 0; mt < 2; mt++)
    #pragma unroll
    for (int h = 0; h < 2; h++) {
        int rl = wmS + mt * 16 + g + h * 8;
        float is = gam * rinv[rl];
        #pragma unroll
        for (int nt = 0; nt < 8; nt++) {
            int cl = wn2 + nt * 8 + tg * 2;
            float2 rf = __half22float2(*(const __half2*)&RB_[(size_t)rl * Ctot + cl]);
            float v0 = acc2[mt][nt][h * 2 + 0] * is + rf.x;
            float v1 = acc2[mt][nt][h * 2 + 1] * is + rf.y;
            if (FUSE5) {
                part[mt * 2 + h] += v0 * w5s[cl] + v1 * w5s[cl + 1];
            } else {
                *(__half2*)&OB[(size_t)rl * Ctot + cl] = __floats2half2_rn(v0, v1);
            }
        }
    }

    if (FUSE5) {
        #pragma unroll
        for (int i = 0; i < 4; i++) {
            part[i] += __shfl_xor_sync(0xffffffffu, part[i], 1);
            part[i] += __shfl_xor_sync(0xffffffffu, part[i], 2);
        }
        if (tg == 0) {
            #pragma unroll
            for (int mt = 0; mt < 2; mt++)
                #pragma unroll
                for (int h = 0; h < 2; h++)
                    rbuf[(wid >> 2) * 128 + wmS + mt * 16 + g + h * 8] = part[mt * 2 + h];
        }
        __syncthreads();
        if (tid < 128) {
            float s = rbuf[tid] + rbuf[128 + tid] + rbuf[256 + tid] + rbuf[384 + tid];
            P5[(size_t)chunk * (BATCH * NPIX) + (size_t)bz * NPIX + m0 + tid] = s;
        }
    }
}

// ---------------------------------------------------------------------------
// conv5 finalize: out[r] = leaky(p5[0][r] + p5[1][r] + b5)
// ---------------------------------------------------------------------------
__global__ void conv5_fin(const float* __restrict__ p5, const float* __restrict__ b5,
                          float* __restrict__ out)
{
    int r = blockIdx.x * 256 + threadIdx.x;
    float v = p5[r] + p5[BATCH * NPIX + r] + b5[0];
    out[r] = v > 0.f ? v : 0.1f * v;
}

// ---------------------------------------------------------------------------
// fused input transpose + conv1
// ---------------------------------------------------------------------------
__global__ void tin_conv1(const float* __restrict__ in, const float* __restrict__ W1,
                          const float* __restrict__ b1, const float* __restrict__ sig,
                          __half* __restrict__ a1)
{
    __shared__ float ws[64 * 6];
    __shared__ float bs[64];
    int t = threadIdx.x;
    float s = sig[0];
    if (t < 64) bs[t] = b1[t];
    for (int i = t; i < 384; i += 256) ws[i] = W1[i] * s;
    __syncthreads();

    int b = blockIdx.y;
    int p = blockIdx.x * 256 + t;
    const float* x = in + (size_t)b * 6 * NPIX + p;
    float xv[6];
    #pragma unroll
    for (int c = 0; c < 6; c++) xv[c] = x[(size_t)c * NPIX];

    __half ho[64];
    #pragma unroll
    for (int o = 0; o < 64; o++) {
        float acc = bs[o];
        #pragma unroll
        for (int c = 0; c < 6; c++) acc += ws[o * 6 + c] * xv[c];
        acc = acc > 0.f ? acc : 0.1f * acc;
        ho[o] = __float2half(acc);
    }
    uint4* dst = (uint4*)(a1 + ((size_t)b * NPIX + p) * 64);
    #pragma unroll
    for (int i = 0; i < 8; i++) dst[i] = ((uint4*)ho)[i];
}

// ---------------------------------------------------------------------------
// spectral norms
// ---------------------------------------------------------------------------
__global__ void snorm_all(const float* __restrict__ W1, const float* __restrict__ u1,
                          const float* __restrict__ W2, const float* __restrict__ u2,
                          const float* __restrict__ W3, const float* __restrict__ u3,
                          const float* __restrict__ W4, const float* __restrict__ u4,
                          const float* __restrict__ W5, const float* __restrict__ u5,
                          float* __restrict__ sig)
{
    __shared__ float vs[512];
    __shared__ float us[512];
    __shared__ float red[256];
    __shared__ float red8[8];

    const float* W; const float* u; int O, C;
    switch (blockIdx.x) {
        case 0: W = W1; u = u1; O = 64;  C = 6;   break;
        case 1: W = W2; u = u2; O = 128; C = 64;  break;
        case 2: W = W3; u = u3; O = 256; C = 128; break;
        case 3: W = W4; u = u4; O = 512; C = 256; break;
        default: W = W5; u = u5; O = 1;  C = 512; break;
    }
    int t = threadIdx.x, lane = t & 31, wid = t >> 5;

    for (int o = t; o < O; o += 256) us[o] = u[o];
    __syncthreads();
    for (int c = t; c < C; c += 256) {
        float s = 0.f;
        #pragma unroll 4
        for (int o = 0; o < O; o++) s += W[(size_t)o * C + c] * us[o];
        vs[c] = s;
    }
    __syncthreads();
    float s = 0.f;
    for (int c = t; c < C; c += 256) s += vs[c] * vs[c];
    red[t] = s; __syncthreads();
    for (int off = 128; off > 0; off >>= 1) { if (t < off) red[t] += red[t + off]; __syncthreads(); }
    float vinv = 1.f / (sqrtf(red[0]) + 1e-12f);
    __syncthreads();
    for (int c = t; c < C; c += 256) vs[c] *= vinv;
    __syncthreads();
    float accq = 0.f;
    for (int o = wid; o < O; o += 8) {
        float tv = 0.f;
        for (int c = lane; c < C; c += 32) tv += W[(size_t)o * C + c] * vs[c];
        #pragma unroll
        for (int off = 16; off > 0; off >>= 1) tv += __shfl_xor_sync(0xffffffffu, tv, off);
        if (lane == 0) accq += tv * tv;
    }
    if (lane == 0) red8[wid] = accq;
    __syncthreads();
    if (t == 0) {
        float S = 0.f;
        #pragma unroll
        for (int w = 0; w < 8; w++) S += red8[w];
        float sigma = S / (sqrtf(S) + 1e-12f);
        sig[blockIdx.x] = 1.f / sigma;
    }
}

// ---------------------------------------------------------------------------
// weight prep
// ---------------------------------------------------------------------------
__global__ void wprep(const float* W2, const float* W3, const float* W4,
                      const float* q1, const float* k1, const float* v1,
                      const float* q2, const float* k2, const float* v2,
                      const float* qb1, const float* kb1,
                      const float* qb2, const float* kb2,
                      const float* sig,
                      __half* o1, __half* o2, __half* o3,
                      __half* qkv1, __half* qkv2,
                      float* d1, float* d2)
{
    if (blockIdx.x == 9) {
        if (blockIdx.y == 0) {
            int t = threadIdx.x;
            if (t < 128) d1[t] = (t < 32) ? qb1[t] : (t < 64 ? kb1[t - 32] : 0.f);
            else { int u = t - 128; d2[u] = (u < 64) ? qb2[u] : kb2[u - 64]; }
        }
        return;
    }
    const float* src; __half* dst; int O, C, Cp; float s = 1.f;
    switch (blockIdx.x) {
        case 0:  src = W2; dst = o1;                O = 128; C = 64;  Cp = 64;  s = sig[1]; break;
        case 1:  src = W3; dst = o2;                O = 256; C = 128; Cp = 128; s = sig[2]; break;
        case 2:  src = W4; dst = o3;                O = 512; C = 256; Cp = 256; s = sig[3]; break;
        case 3:  src = q1; dst = qkv1;              O = 32;  C = 256; Cp = 256; break;
        case 4:  src = k1; dst = qkv1 + 32 * 256;   O = 32;  C = 256; Cp = 256; break;
        case 5:  src = q1; dst = qkv1 + 64 * 256;   O = 64;  C = 0;   Cp = 256; break; // zero pad
        case 6:  src = v1; dst = qkv1 + 128 * 256;  O = 256; C = 256; Cp = 256; break;
        case 7:  src = q2; dst = qkv2;              O = 64;  C = 512; Cp = 512; break;
        case 8:  src = k2; dst = qkv2 + 64 * 512;   O = 64;  C = 512; Cp = 512; break;
        default: src = v2; dst = qkv2 + 128 * 512;  O = 512; C = 512; Cp = 512; break;
    }
    int total = O * Cp;
    for (int i = blockIdx.y * 256 + threadIdx.x; i < total; i += 8 * 256) {
        int o = i / Cp, c = i % Cp;
        float v = (c < C) ? src[(size_t)o * C + c] * s : 0.f;
        dst[i] = __float2half(v);
    }
}

// ---------------------------------------------------------------------------
// kernel_launch
// ---------------------------------------------------------------------------
extern "C" void kernel_launch(void* const* d_in, const int* in_sizes, int n_in,
                              void* d_out, int out_size)
{
    const float* inp  = (const float*)d_in[0];
    const float* W1 = (const float*)d_in[1];  const float* b1 = (const float*)d_in[2];  const float* u1 = (const float*)d_in[3];
    const float* W2 = (const float*)d_in[4];  const float* b2 = (const float*)d_in[5];  const float* u2 = (const float*)d_in[6];
    const float* W3 = (const float*)d_in[7];  const float* b3 = (const float*)d_in[8];  const float* u3 = (const float*)d_in[9];
    const float* W4 = (const float*)d_in[10]; const float* b4 = (const float*)d_in[11]; const float* u4 = (const float*)d_in[12];
    const float* W5 = (const float*)d_in[13]; const float* b5 = (const float*)d_in[14]; const float* u5 = (const float*)d_in[15];
    const float* a1qW = (const float*)d_in[16]; const float* a1qb = (const float*)d_in[17];
    const float* a1kW = (const float*)d_in[18]; const float* a1kb = (const float*)d_in[19];
    const float* a1vW = (const float*)d_in[20]; const float* a1vb = (const float*)d_in[21];
    const float* a1g  = (const float*)d_in[22];
    const float* a2qW = (const float*)d_in[23]; const float* a2qb = (const float*)d_in[24];
    const float* a2kW = (const float*)d_in[25]; const float* a2kb = (const float*)d_in[26];
    const float* a2vW = (const float*)d_in[27]; const float* a2vb = (const float*)d_in[28];
    const float* a2g  = (const float*)d_in[29];

    __half *a1h, *a3h, *qkh, *vh, *t1h, *a4h;
    __half *W2h, *W3h, *W4h, *qkv1h, *qkv2h;
    float *sig, *qkb1, *qkb2, *p5;
    cudaGetSymbolAddress((void**)&a1h, g_a1);
    cudaGetSymbolAddress((void**)&a3h, g_a3);
    cudaGetSymbolAddress((void**)&qkh, g_qk);
    cudaGetSymbolAddress((void**)&vh,  g_v);
    cudaGetSymbolAddress((void**)&t1h, g_t1);
    cudaGetSymbolAddress((void**)&a4h, g_a4);
    cudaGetSymbolAddress((void**)&p5,  g_p5);
    cudaGetSymbolAddress((void**)&sig, g_sig);
    cudaGetSymbolAddress((void**)&qkb1, g_qkb1);
    cudaGetSymbolAddress((void**)&qkb2, g_qkb2);
    cudaGetSymbolAddress((void**)&W2h, g_W2h);
    cudaGetSymbolAddress((void**)&W3h, g_W3h);
    cudaGetSymbolAddress((void**)&W4h, g_W4h);
    cudaGetSymbolAddress((void**)&qkv1h, g_qkv1h);
    cudaGetSymbolAddress((void**)&qkv2h, g_qkv2h);

    const int SMEMSZ = 98304;
    const int C23SM = 131072;
    cudaFuncSetAttribute(hgemm<0>, cudaFuncAttributeMaxDynamicSharedMemorySize, SMEMSZ);
    cudaFuncSetAttribute(hgemm<7>, cudaFuncAttributeMaxDynamicSharedMemorySize, SMEMSZ);
    cudaFuncSetAttribute(conv23, cudaFuncAttributeMaxDynamicSharedMemorySize, C23SM);
    cudaFuncSetAttribute((const void*)flash<32,0>, cudaFuncAttributeMaxDynamicSharedMemorySize, FSMEM);
    cudaFuncSetAttribute((const void*)flash<64,1>, cudaFuncAttributeMaxDynamicSharedMemorySize, FSMEM);

    const size_t NP = NPIX;
    auto gd = [&](int Nn) { return dim3((Nn + 127) / 128, NPIX / 128, BATCH); };

    snorm_all<<<5, 256>>>(W1, u1, W2, u2, W3, u3, W4, u4, W5, u5, sig);
    wprep<<<dim3(11, 8), 256>>>(W2, W3, W4, a1qW, a1kW, a1vW, a2qW, a2kW, a2vW,
                                a1qb, a1kb, a2qb, a2kb, sig,
                                W2h, W3h, W4h, qkv1h, qkv2h, qkb1, qkb2);

    // fused transpose + conv1
    tin_conv1<<<dim3(16, BATCH), 256>>>(inp, W1, b1, sig, a1h);

    // fused conv2 + conv3
    conv23<<<dim3(32, BATCH), 512, C23SM>>>(a1h, W2h, W3h, b2, b3, a3h);

    // attention 1: merged q|k|v conv (N = 128 qk + 256 v), then flash -> t1
    hgemm<7><<<gd(384), 256, SMEMSZ>>>(a3h, qkv1h, qkh, vh, NPIX, 384, 256, 256, 256, 128,
        NP * 256, 0, NP * 128, 256 * NP, 1, qkb1, a1vb);
    flash<32,0><<<dim3(1, 32, BATCH), 512, FSMEM>>>(qkh, vh, a3h, t1h, a1g, 256,
        nullptr, nullptr, nullptr);

    // conv4
    hgemm<0><<<gd(512), 256, SMEMSZ>>>(t1h, W4h, a4h, nullptr, NPIX, 512, 256, 256, 256, 512,
        NP * 256, 0, NP * 512, 0, 0, b4, nullptr);

    // attention 2: merged q|k|v conv, then flash with fused conv5 partials
    hgemm<7><<<gd(640), 256, SMEMSZ>>>(a4h, qkv2h, qkh, vh, NPIX, 640, 512, 512, 512, 128,
        NP * 512, 0, NP * 128, 512 * NP, 1, qkb2, a2vb);
    flash<64,1><<<dim3(2, 32, BATCH), 512, FSMEM>>>(qkh, vh, a4h, nullptr, a2g, 512,
        W5, sig, p5);

    // conv5 finalize -> f32 output (B, 4096)
    conv5_fin<<<BATCH * NPIX / 256, 256>>>(p5, b5, (float*)d_out);
}